// round 8
// baseline (speedup 1.0000x reference)
#include <cuda_runtime.h>
#include <cuda_bf16.h>
#include <cstdint>

#define B_ 4
#define N_ 4096
#define C_ 64
#define H_ 4
#define DH_ 16
#define M_ 256
#define KNN_ 10
#define KS_ 4
#define ROWS_ (B_ * N_)   // 16384

// ---------------- scratch (device globals; no runtime alloc allowed) ------
__device__ float g_qkv[ROWS_ * 3 * C_];   // [B,N,3C] : q|k|v per row
__device__ int   g_nbr[ROWS_ * KNN_];     // [B,N,10]
__device__ float g_o  [ROWS_ * C_];       // attention output (pre-proj)
__device__ float g_x1 [ROWS_ * C_];       // residual after attn
__device__ unsigned char g_mask[ROWS_];   // canonical 0/1 mask

// ================= Kernel 0: normalize mask dtype =========================
// The harness transports the bool mask as int32/float32 (or possibly uint8).
// Detect the element width from the data itself, then write canonical bytes.
// Detection reads only the first 16384 bytes (valid under either layout):
// a 4-byte layout has every u32 word in {0, 1, 0x3f800000}; a genuine byte
// layout almost surely does not (p ~ 8^-4096).
__global__ void k_maskfix(const unsigned char* __restrict__ raw)
{
    __shared__ int s_bytes;                 // 1 => 1-byte layout
    int tid = threadIdx.x;                  // single block of 1024
    if (tid == 0) s_bytes = 0;
    __syncthreads();
    const unsigned int* w = reinterpret_cast<const unsigned int*>(raw);
    int bad = 0;
    #pragma unroll
    for (int i = 0; i < 4; i++) {           // words 0..4095 = first 16KB
        unsigned int v = w[tid + 1024 * i];
        if (v != 0u && v != 1u && v != 0x3f800000u) bad = 1;
    }
    if (bad) s_bytes = 1;
    __syncthreads();
    if (s_bytes) {
        #pragma unroll
        for (int i = 0; i < 16; i++) {
            int idx = tid + 1024 * i;
            g_mask[idx] = raw[idx] ? 1 : 0;
        }
    } else {
        #pragma unroll
        for (int i = 0; i < 16; i++) {
            int idx = tid + 1024 * i;
            g_mask[idx] = (w[idx] != 0u) ? 1 : 0;   // handles int32 and fp32
        }
    }
}

// ======================= Kernel 1: LN1 + QKV GEMM =========================
// block: 256 threads, 8 rows per block. w_qkv (64x192) staged in smem.
extern __shared__ float dyn_smem[];

__global__ void k_ln_qkv(const float* __restrict__ x,
                         const float* __restrict__ g1, const float* __restrict__ b1,
                         const float* __restrict__ wqkv, const float* __restrict__ bqkv)
{
    float* sw = dyn_smem;            // 64*192
    float* sb = sw + 64 * 192;       // 192
    float* sx = sb + 192;            // 8*64
    int tid = threadIdx.x;
    for (int i = tid; i < 64 * 192; i += 256) sw[i] = wqkv[i];
    if (tid < 192) sb[tid] = bqkv[tid];

    int row0 = blockIdx.x * 8;
    int wid = tid >> 5, lane = tid & 31;
    {
        int r = row0 + wid;
        const float* xr = x + (size_t)r * 64;
        float a0 = xr[lane], a1 = xr[lane + 32];
        float s = a0 + a1;
        #pragma unroll
        for (int off = 16; off; off >>= 1) s += __shfl_xor_sync(0xffffffffu, s, off);
        float mean = s * (1.f / 64.f);
        float d0 = a0 - mean, d1 = a1 - mean;
        float vs = d0 * d0 + d1 * d1;
        #pragma unroll
        for (int off = 16; off; off >>= 1) vs += __shfl_xor_sync(0xffffffffu, vs, off);
        float inv = rsqrtf(vs * (1.f / 64.f) + 1e-5f);
        sx[wid * 64 + lane]      = d0 * inv * g1[lane]      + b1[lane];
        sx[wid * 64 + lane + 32] = d1 * inv * g1[lane + 32] + b1[lane + 32];
    }
    __syncthreads();

    #pragma unroll
    for (int i = 0; i < 6; i++) {
        int o = tid + 256 * i;            // 8*192 = 1536 outputs
        int r = o / 192, c = o % 192;
        float acc = sb[c];
        const float* xr = &sx[r * 64];
        #pragma unroll
        for (int k = 0; k < 64; k++) acc += xr[k] * sw[k * 192 + c];
        g_qkv[(size_t)(row0 + r) * 192 + c] = acc;
    }
}

// ======================= Kernel 2: KNN (top-10 by d2) =====================
// block: 512 threads = 16 warps = 16 queries. Batch coords staged in smem.
// Masked voxels get x += 1e5 => d2 >= ~1e10 > any valid d2 (<= 768); valid
// count ~2048 >> 10, so masked entries never enter top-10 (matches BIG mask).
__global__ void k_knn(const float* __restrict__ coords)
{
    float* sx = dyn_smem;        // 4096
    float* sy = sx + N_;         // 4096
    float* sz = sy + N_;         // 4096
    int b    = blockIdx.x >> 8;          // 256 tiles per batch
    int tile = blockIdx.x & 255;
    int tid = threadIdx.x;
    const float* cb = coords + (size_t)b * N_ * 3;
    const unsigned char* mb = g_mask + (size_t)b * N_;
    for (int i = tid; i < N_; i += 512) {
        float cx = cb[3 * i], cy = cb[3 * i + 1], cz = cb[3 * i + 2];
        if (!mb[i]) cx += 1e5f;
        sx[i] = cx; sy[i] = cy; sz[i] = cz;
    }
    __syncthreads();

    int wid = tid >> 5, lane = tid & 31;
    int n = tile * 16 + wid;
    float qx = sx[n], qy = sy[n], qz = sz[n];

    float d[KNN_]; int id[KNN_];
    #pragma unroll
    for (int s = 0; s < KNN_; s++) { d[s] = 3.4e38f; id[s] = 0x7fffffff; }

    #pragma unroll 4
    for (int t = 0; t < N_ / 32; t++) {
        int j = t * 32 + lane;
        float dx = qx - sx[j], dy = qy - sy[j], dz = qz - sz[j];
        float d2 = dx * dx + dy * dy + dz * dz;
        if (d2 < d[KNN_ - 1] || (d2 == d[KNN_ - 1] && j < id[KNN_ - 1])) {
            float cd = d2; int ci = j;
            #pragma unroll
            for (int s = 0; s < KNN_; s++) {
                bool lt = (cd < d[s]) || (cd == d[s] && ci < id[s]);
                if (lt) { float td = d[s]; int ti = id[s]; d[s] = cd; id[s] = ci; cd = td; ci = ti; }
            }
        }
    }

    // warp pop-merge of 32 sorted lists -> global top-10 (stable by index)
    int p = 0;
    int* outp = g_nbr + ((size_t)b * N_ + n) * KNN_;
    for (int r = 0; r < KNN_; r++) {
        float hv = (p < KNN_) ? d[p] : 3.4e38f;
        int   hi = (p < KNN_) ? id[p] : 0x7fffffff;
        float mv = hv; int mi = hi;
        #pragma unroll
        for (int off = 16; off; off >>= 1) {
            float ov = __shfl_xor_sync(0xffffffffu, mv, off);
            int   oi = __shfl_xor_sync(0xffffffffu, mi, off);
            if (ov < mv || (ov == mv && oi < mi)) { mv = ov; mi = oi; }
        }
        if (hv == mv && hi == mi) p++;   // unique winner (indices distinct)
        if (lane == 0) outp[r] = mi;
    }
}

// =================== Kernel 3: sparse dynamic attention ===================
// one warp per (b, n, h). scores over 10 neighbors, stable top-4, softmax,
// weighted V gather. Output -> g_o [B,N,C].
__global__ void k_attn()
{
    int g = blockIdx.x * 8 + (threadIdx.x >> 5);
    int lane = threadIdx.x & 31;
    int h = g & 3;
    int n = (g >> 2) & (N_ - 1);
    int b = g >> 14;
    size_t rowbase = (size_t)(b * N_ + n) * 192;

    float qv = (lane < 16) ? g_qkv[rowbase + h * 16 + lane] : 0.f;

    int nbrj = n;
    if (lane < KNN_) nbrj = g_nbr[((size_t)b * N_ + n) * KNN_ + lane];

    const float4* krow = reinterpret_cast<const float4*>(
        g_qkv + ((size_t)b * N_ + nbrj) * 192 + 64 + h * 16);
    float4 k0 = krow[0], k1 = krow[1], k2 = krow[2], k3 = krow[3];
    float kk[16] = {k0.x,k0.y,k0.z,k0.w, k1.x,k1.y,k1.z,k1.w,
                    k2.x,k2.y,k2.z,k2.w, k3.x,k3.y,k3.z,k3.w};
    float acc = 0.f;
    #pragma unroll
    for (int dd = 0; dd < 16; dd++) {
        float qd = __shfl_sync(0xffffffffu, qv, dd);
        acc += qd * kk[dd];
    }
    float s = acc * 0.25f;                     // 1/sqrt(16)
    if (lane < KNN_) {
        if (!g_mask[b * N_ + nbrj]) s -= 1e9f;
    } else {
        s = -3.4e38f;
    }

    // stable top-4 (max value, tie -> smaller lane/k index)
    float sv[KS_]; int si[KS_];
    float cur = s;
    #pragma unroll
    for (int r = 0; r < KS_; r++) {
        float mv = cur; int mi = lane;
        #pragma unroll
        for (int off = 16; off; off >>= 1) {
            float ov = __shfl_xor_sync(0xffffffffu, mv, off);
            int   oi = __shfl_xor_sync(0xffffffffu, mi, off);
            if (ov > mv || (ov == mv && oi < mi)) { mv = ov; mi = oi; }
        }
        sv[r] = mv; si[r] = mi;
        if (lane == mi) cur = -3.4e38f;
    }

    float mx = sv[0];
    float w0 = expf(sv[0] - mx), w1 = expf(sv[1] - mx);
    float w2 = expf(sv[2] - mx), w3 = expf(sv[3] - mx);
    float inv = 1.f / (w0 + w1 + w2 + w3);
    w0 *= inv; w1 *= inv; w2 *= inv; w3 *= inv;

    int nb0 = __shfl_sync(0xffffffffu, nbrj, si[0]);
    int nb1 = __shfl_sync(0xffffffffu, nbrj, si[1]);
    int nb2 = __shfl_sync(0xffffffffu, nbrj, si[2]);
    int nb3 = __shfl_sync(0xffffffffu, nbrj, si[3]);

    if (lane < 16) {
        size_t voff = (size_t)b * N_ * 192 + 128 + h * 16 + lane;
        float o = w0 * g_qkv[voff + (size_t)nb0 * 192]
                + w1 * g_qkv[voff + (size_t)nb1 * 192]
                + w2 * g_qkv[voff + (size_t)nb2 * 192]
                + w3 * g_qkv[voff + (size_t)nb3 * 192];
        g_o[(size_t)(b * N_ + n) * 64 + h * 16 + lane] = o;
    }
}

// =================== Kernel 4: proj + mask + residual =====================
__global__ void k_proj(const float* __restrict__ x,
                       const float* __restrict__ wp, const float* __restrict__ bp)
{
    __shared__ float sw[64 * 64];
    __shared__ float so[32 * 64];
    __shared__ float sbp[64];
    int tid = threadIdx.x;
    for (int i = tid; i < 4096; i += 256) sw[i] = wp[i];
    if (tid < 64) sbp[tid] = bp[tid];
    int row0 = blockIdx.x * 32;
    for (int i = tid; i < 32 * 64; i += 256) so[i] = g_o[(size_t)row0 * 64 + i];
    __syncthreads();

    #pragma unroll
    for (int i = 0; i < 8; i++) {
        int o = tid + 256 * i;
        int r = o >> 6, c = o & 63;
        float acc = sbp[c];
        const float* orow = &so[r * 64];
        #pragma unroll
        for (int k = 0; k < 64; k++) acc += orow[k] * sw[k * 64 + c];
        int grow = row0 + r;
        float a = g_mask[grow] ? acc : 0.f;
        g_x1[(size_t)grow * 64 + c] = 0.5f * a + x[(size_t)grow * 64 + c];
    }
}

// ============ Kernel 5: LN2 + MLP (64->256 gelu ->64) + residual ==========
// block: 512 threads, 64 rows per block (4 groups of 16). w1,w2 in smem.
__device__ __forceinline__ float gelu_tanh(float v)
{
    float c = 0.7978845608028654f * (v + 0.044715f * v * v * v);
    return 0.5f * v * (1.f + tanhf(c));
}

__global__ void k_mlp(const float* __restrict__ g2, const float* __restrict__ b2p,
                      const float* __restrict__ w1, const float* __restrict__ bb1,
                      const float* __restrict__ w2, const float* __restrict__ bb2,
                      float* __restrict__ out)
{
    float* sw1 = dyn_smem;             // 64*256
    float* sw2 = sw1 + 64 * 256;       // 256*64
    float* sb1 = sw2 + 256 * 64;       // 256
    float* sb2 = sb1 + 256;            // 64
    float* sx  = sb2 + 64;             // 16*64
    float* sh  = sx + 16 * 64;         // 16*256
    int tid = threadIdx.x;
    for (int i = tid; i < 64 * 256; i += 512) { sw1[i] = w1[i]; sw2[i] = w2[i]; }
    if (tid < 256) sb1[tid] = bb1[tid];
    if (tid < 64)  sb2[tid] = bb2[tid];
    __syncthreads();

    int wid = tid >> 5, lane = tid & 31;
    int row0 = blockIdx.x * 64;

    for (int grp = 0; grp < 4; grp++) {
        int rbase = row0 + grp * 16;
        // LN2 : warp w handles row rbase+w (warps 0..15)
        {
            int r = rbase + wid;
            const float* xr = g_x1 + (size_t)r * 64;
            float a0 = xr[lane], a1 = xr[lane + 32];
            float s = a0 + a1;
            #pragma unroll
            for (int off = 16; off; off >>= 1) s += __shfl_xor_sync(0xffffffffu, s, off);
            float mean = s * (1.f / 64.f);
            float d0 = a0 - mean, d1 = a1 - mean;
            float vs = d0 * d0 + d1 * d1;
            #pragma unroll
            for (int off = 16; off; off >>= 1) vs += __shfl_xor_sync(0xffffffffu, vs, off);
            float inv = rsqrtf(vs * (1.f / 64.f) + 1e-5f);
            sx[wid * 64 + lane]      = d0 * inv * g2[lane]      + b2p[lane];
            sx[wid * 64 + lane + 32] = d1 * inv * g2[lane + 32] + b2p[lane + 32];
        }
        __syncthreads();

        // h1 = gelu(xn @ w1 + b1) : 16*256 outputs, 8 per thread
        {
            int c = tid & 255;
            int rb = tid >> 8;          // 0 or 1
            #pragma unroll
            for (int i = 0; i < 8; i++) {
                int r = rb + 2 * i;
                float acc = sb1[c];
                const float* xr = &sx[r * 64];
                #pragma unroll
                for (int k = 0; k < 64; k++) acc += xr[k] * sw1[k * 256 + c];
                sh[r * 256 + c] = gelu_tanh(acc);
            }
        }
        __syncthreads();

        // out = 0.5*(h1 @ w2 + b2) + x1 : 16*64 outputs, 2 per thread
        {
            #pragma unroll
            for (int i = 0; i < 2; i++) {
                int o = tid + 512 * i;
                int r = o >> 6, c = o & 63;
                float acc = sb2[c];
                const float* hr = &sh[r * 256];
                #pragma unroll 8
                for (int k = 0; k < 256; k++) acc += hr[k] * sw2[k * 64 + c];
                size_t gidx = (size_t)(rbase + r) * 64 + c;
                out[gidx] = 0.5f * acc + g_x1[gidx];
            }
        }
        __syncthreads();
    }
}

// ============================== launcher ==================================
extern "C" void kernel_launch(void* const* d_in, const int* in_sizes, int n_in,
                              void* d_out, int out_size)
{
    const float* x      = (const float*)d_in[0];
    const float* coords = (const float*)d_in[1];
    const unsigned char* mask_raw = (const unsigned char*)d_in[2];
    const float* ln1g = (const float*)d_in[3];
    const float* ln1b = (const float*)d_in[4];
    const float* ln2g = (const float*)d_in[5];
    const float* ln2b = (const float*)d_in[6];
    const float* wqkv = (const float*)d_in[7];
    const float* bqkv = (const float*)d_in[8];
    const float* wproj = (const float*)d_in[9];
    const float* bproj = (const float*)d_in[10];
    const float* w1 = (const float*)d_in[11];
    const float* b1 = (const float*)d_in[12];
    const float* w2 = (const float*)d_in[13];
    const float* b2 = (const float*)d_in[14];
    float* out = (float*)d_out;

    static bool attr_done = false;
    if (!attr_done) {
        cudaFuncSetAttribute(k_ln_qkv, cudaFuncAttributeMaxDynamicSharedMemorySize, 56 * 1024);
        cudaFuncSetAttribute(k_knn,    cudaFuncAttributeMaxDynamicSharedMemorySize, 52 * 1024);
        cudaFuncSetAttribute(k_mlp,    cudaFuncAttributeMaxDynamicSharedMemorySize, 168 * 1024);
        attr_done = true;
    }

    k_maskfix<<<1, 1024>>>(mask_raw);

    size_t smem_qkv = (64 * 192 + 192 + 8 * 64) * sizeof(float);
    k_ln_qkv<<<ROWS_ / 8, 256, smem_qkv>>>(x, ln1g, ln1b, wqkv, bqkv);

    size_t smem_knn = (size_t)3 * N_ * sizeof(float);
    k_knn<<<B_ * (N_ / 16), 512, smem_knn>>>(coords);

    k_attn<<<(ROWS_ * H_) / 8, 256>>>();

    k_proj<<<ROWS_ / 32, 256>>>(x, wproj, bproj);

    size_t smem_mlp = (64 * 256 + 256 * 64 + 256 + 64 + 16 * 64 + 16 * 256) * sizeof(float);
    k_mlp<<<ROWS_ / 64, 512, smem_mlp>>>(ln2g, ln2b, w1, b1, w2, b2, out);
}

// round 9
// speedup vs baseline: 2.4313x; 2.4313x over previous
#include <cuda_runtime.h>
#include <cuda_bf16.h>
#include <cstdint>

#define B_ 4
#define N_ 4096
#define C_ 64
#define H_ 4
#define DH_ 16
#define M_ 256
#define KNN_ 10
#define KS_ 4
#define ROWS_ (B_ * N_)   // 16384

// ---------------- scratch (device globals; no runtime alloc allowed) ------
__device__ float g_qkv[ROWS_ * 3 * C_];   // [B,N,3C] : q|k|v per row
__device__ int   g_nbr[ROWS_ * KNN_];     // [B,N,10]
__device__ float g_o  [ROWS_ * C_];       // attention output (pre-proj)
__device__ float g_x1 [ROWS_ * C_];       // residual after attn
__device__ unsigned char g_mask[ROWS_];   // canonical 0/1 mask

extern __shared__ float dyn_smem[];

// ================= Kernel 0: normalize mask dtype =========================
__global__ void k_maskfix(const unsigned char* __restrict__ raw)
{
    __shared__ int s_bytes;                 // 1 => 1-byte layout
    int tid = threadIdx.x;                  // single block of 1024
    if (tid == 0) s_bytes = 0;
    __syncthreads();
    const unsigned int* w = reinterpret_cast<const unsigned int*>(raw);
    int bad = 0;
    #pragma unroll
    for (int i = 0; i < 4; i++) {           // words 0..4095 = first 16KB
        unsigned int v = w[tid + 1024 * i];
        if (v != 0u && v != 1u && v != 0x3f800000u) bad = 1;
    }
    if (bad) s_bytes = 1;
    __syncthreads();
    if (s_bytes) {
        #pragma unroll
        for (int i = 0; i < 16; i++) {
            int idx = tid + 1024 * i;
            g_mask[idx] = raw[idx] ? 1 : 0;
        }
    } else {
        #pragma unroll
        for (int i = 0; i < 16; i++) {
            int idx = tid + 1024 * i;
            g_mask[idx] = (w[idx] != 0u) ? 1 : 0;
        }
    }
}

// -------- helper: 16-lane reduction (half-warp, xor offsets < 16) ---------
__device__ __forceinline__ float hsum16(float s)
{
    s += __shfl_xor_sync(0xffffffffu, s, 8);
    s += __shfl_xor_sync(0xffffffffu, s, 4);
    s += __shfl_xor_sync(0xffffffffu, s, 2);
    s += __shfl_xor_sync(0xffffffffu, s, 1);
    return s;
}

// ======================= Kernel 1: LN1 + QKV GEMM =========================
// 512 threads, 32 rows/block, grid 512. tile = 2 rows x 6 cols per thread.
__global__ __launch_bounds__(512, 1)
void k_ln_qkv(const float* __restrict__ x,
              const float* __restrict__ g1, const float* __restrict__ b1,
              const float* __restrict__ wqkv, const float* __restrict__ bqkv)
{
    float* sw = dyn_smem;            // [64][192] = 12288
    float* sx = sw + 12288;          // [32][65]  = 2080  (65: bank spread)
    float* sb = sx + 2080;           // 192
    int tid = threadIdx.x;
    for (int i = tid; i < 12288 / 4; i += 512)
        reinterpret_cast<float4*>(sw)[i] = reinterpret_cast<const float4*>(wqkv)[i];
    if (tid < 192) sb[tid] = bqkv[tid];

    int row0 = blockIdx.x * 32;
    int wid = tid >> 5, lane = tid & 31;
    {   // LN: half-warp per row (16 warps x 2 rows = 32)
        int r  = 2 * wid + (lane >> 4);
        int c4 = (lane & 15) * 4;
        const float4 xv = *reinterpret_cast<const float4*>(x + (size_t)(row0 + r) * 64 + c4);
        float s = hsum16(xv.x + xv.y + xv.z + xv.w);
        float mean = s * (1.f / 64.f);
        float d0 = xv.x - mean, d1 = xv.y - mean, d2 = xv.z - mean, d3 = xv.w - mean;
        float vs = hsum16(d0 * d0 + d1 * d1 + d2 * d2 + d3 * d3);
        float inv = rsqrtf(vs * (1.f / 64.f) + 1e-5f);
        sx[r * 65 + c4 + 0] = d0 * inv * g1[c4 + 0] + b1[c4 + 0];
        sx[r * 65 + c4 + 1] = d1 * inv * g1[c4 + 1] + b1[c4 + 1];
        sx[r * 65 + c4 + 2] = d2 * inv * g1[c4 + 2] + b1[c4 + 2];
        sx[r * 65 + c4 + 3] = d3 * inv * g1[c4 + 3] + b1[c4 + 3];
    }
    __syncthreads();

    int r0 = (tid & 15) * 2;
    int c0 = (tid >> 4) * 6;
    float acc[2][6];
    #pragma unroll
    for (int j = 0; j < 6; j++) { acc[0][j] = sb[c0 + j]; acc[1][j] = sb[c0 + j]; }
    #pragma unroll 16
    for (int k = 0; k < 64; k++) {
        float x0 = sx[r0 * 65 + k];
        float x1 = sx[(r0 + 1) * 65 + k];
        const float* wr = &sw[k * 192 + c0];
        float2 w0 = *reinterpret_cast<const float2*>(wr);
        float2 w1 = *reinterpret_cast<const float2*>(wr + 2);
        float2 w2 = *reinterpret_cast<const float2*>(wr + 4);
        acc[0][0] += x0 * w0.x; acc[0][1] += x0 * w0.y;
        acc[0][2] += x0 * w1.x; acc[0][3] += x0 * w1.y;
        acc[0][4] += x0 * w2.x; acc[0][5] += x0 * w2.y;
        acc[1][0] += x1 * w0.x; acc[1][1] += x1 * w0.y;
        acc[1][2] += x1 * w1.x; acc[1][3] += x1 * w1.y;
        acc[1][4] += x1 * w2.x; acc[1][5] += x1 * w2.y;
    }
    #pragma unroll
    for (int i = 0; i < 2; i++) {
        float* outp = g_qkv + (size_t)(row0 + r0 + i) * 192 + c0;
        #pragma unroll
        for (int j = 0; j < 6; j++) outp[j] = acc[i][j];
    }
}

// ======================= Kernel 2: KNN (two-pass) =========================
// 512 threads = 16 warps = 16 queries. Coords as float4 in smem (64KB).
// Pass A: per-lane min. T = 10th-smallest of lane minima (>= global v10).
// Pass B: only candidates d2 <= T enter the insert path (uniform branch).
__global__ __launch_bounds__(512)
void k_knn(const float* __restrict__ coords)
{
    float4* sc = reinterpret_cast<float4*>(dyn_smem);   // 4096 float4
    int b    = blockIdx.x >> 8;
    int tile = blockIdx.x & 255;
    int tid = threadIdx.x;
    const float* cb = coords + (size_t)b * N_ * 3;
    const unsigned char* mb = g_mask + (size_t)b * N_;
    for (int i = tid; i < N_; i += 512) {
        float cx = cb[3 * i], cy = cb[3 * i + 1], cz = cb[3 * i + 2];
        if (!mb[i]) cx += 1e5f;    // masked pushed far; valid count >> 10
        sc[i] = make_float4(cx, cy, cz, 0.f);
    }
    __syncthreads();

    int wid = tid >> 5, lane = tid & 31;
    int n = tile * 16 + wid;
    float4 q = sc[n];

    // ---- pass A: per-lane minimum over its 128 candidates
    float mA = 3.4e38f;
    #pragma unroll 4
    for (int t = 0; t < N_ / 32; t++) {
        float4 p = sc[t * 32 + lane];
        float dx = q.x - p.x, dy = q.y - p.y, dz = q.z - p.z;
        float d2 = dx * dx + dy * dy + dz * dz;
        mA = fminf(mA, d2);
    }

    // ---- T = 10th smallest of 32 lane minima
    float cur = mA, T = 0.f;
    #pragma unroll
    for (int r = 0; r < KNN_; r++) {
        float mv = cur;
        #pragma unroll
        for (int off = 16; off; off >>= 1)
            mv = fminf(mv, __shfl_xor_sync(0xffffffffu, mv, off));
        unsigned bal = __ballot_sync(0xffffffffu, cur == mv);
        if (lane == (__ffs(bal) - 1)) cur = 3.4e38f;
        T = mv;
    }

    // ---- pass B: thresholded sorted insert
    float d[KNN_]; int id[KNN_];
    #pragma unroll
    for (int s = 0; s < KNN_; s++) { d[s] = 3.4e38f; id[s] = 0x7fffffff; }

    #pragma unroll 2
    for (int t = 0; t < N_ / 32; t++) {
        int j = t * 32 + lane;
        float4 p = sc[j];
        float dx = q.x - p.x, dy = q.y - p.y, dz = q.z - p.z;
        float d2 = dx * dx + dy * dy + dz * dz;
        bool ins = (d2 <= T) &&
                   (d2 < d[KNN_ - 1] || (d2 == d[KNN_ - 1] && j < id[KNN_ - 1]));
        if (__any_sync(0xffffffffu, ins)) {
            if (ins) {
                float cd = d2; int ci = j;
                #pragma unroll
                for (int s = 0; s < KNN_; s++) {
                    bool lt = (cd < d[s]) || (cd == d[s] && ci < id[s]);
                    if (lt) { float td = d[s]; int ti = id[s];
                              d[s] = cd; id[s] = ci; cd = td; ci = ti; }
                }
            }
        }
    }

    // ---- warp pop-merge of sorted lane lists -> global top-10
    int p = 0;
    int* outp = g_nbr + ((size_t)b * N_ + n) * KNN_;
    for (int r = 0; r < KNN_; r++) {
        float hv = (p < KNN_) ? d[p] : 3.4e38f;
        int   hi = (p < KNN_) ? id[p] : 0x7fffffff;
        float mv = hv; int mi = hi;
        #pragma unroll
        for (int off = 16; off; off >>= 1) {
            float ov = __shfl_xor_sync(0xffffffffu, mv, off);
            int   oi = __shfl_xor_sync(0xffffffffu, mi, off);
            if (ov < mv || (ov == mv && oi < mi)) { mv = ov; mi = oi; }
        }
        if (hv == mv && hi == mi) p++;
        if (lane == 0) outp[r] = mi;
    }
}

// =================== Kernel 3: sparse dynamic attention ===================
__global__ void k_attn()
{
    int g = blockIdx.x * 8 + (threadIdx.x >> 5);
    int lane = threadIdx.x & 31;
    int h = g & 3;
    int n = (g >> 2) & (N_ - 1);
    int b = g >> 14;
    size_t rowbase = (size_t)(b * N_ + n) * 192;

    float qv = (lane < 16) ? g_qkv[rowbase + h * 16 + lane] : 0.f;

    int nbrj = n;
    if (lane < KNN_) nbrj = g_nbr[((size_t)b * N_ + n) * KNN_ + lane];

    const float4* krow = reinterpret_cast<const float4*>(
        g_qkv + ((size_t)b * N_ + nbrj) * 192 + 64 + h * 16);
    float4 k0 = krow[0], k1 = krow[1], k2 = krow[2], k3 = krow[3];
    float kk[16] = {k0.x,k0.y,k0.z,k0.w, k1.x,k1.y,k1.z,k1.w,
                    k2.x,k2.y,k2.z,k2.w, k3.x,k3.y,k3.z,k3.w};
    float acc = 0.f;
    #pragma unroll
    for (int dd = 0; dd < 16; dd++) {
        float qd = __shfl_sync(0xffffffffu, qv, dd);
        acc += qd * kk[dd];
    }
    float s = acc * 0.25f;
    if (lane < KNN_) {
        if (!g_mask[b * N_ + nbrj]) s -= 1e9f;
    } else {
        s = -3.4e38f;
    }

    float sv[KS_]; int si[KS_];
    float cur = s;
    #pragma unroll
    for (int r = 0; r < KS_; r++) {
        float mv = cur; int mi = lane;
        #pragma unroll
        for (int off = 16; off; off >>= 1) {
            float ov = __shfl_xor_sync(0xffffffffu, mv, off);
            int   oi = __shfl_xor_sync(0xffffffffu, mi, off);
            if (ov > mv || (ov == mv && oi < mi)) { mv = ov; mi = oi; }
        }
        sv[r] = mv; si[r] = mi;
        if (lane == mi) cur = -3.4e38f;
    }

    float mx = sv[0];
    float w0 = expf(sv[0] - mx), w1 = expf(sv[1] - mx);
    float w2 = expf(sv[2] - mx), w3 = expf(sv[3] - mx);
    float inv = 1.f / (w0 + w1 + w2 + w3);
    w0 *= inv; w1 *= inv; w2 *= inv; w3 *= inv;

    int nb0 = __shfl_sync(0xffffffffu, nbrj, si[0]);
    int nb1 = __shfl_sync(0xffffffffu, nbrj, si[1]);
    int nb2 = __shfl_sync(0xffffffffu, nbrj, si[2]);
    int nb3 = __shfl_sync(0xffffffffu, nbrj, si[3]);

    if (lane < 16) {
        size_t voff = (size_t)b * N_ * 192 + 128 + h * 16 + lane;
        float o = w0 * g_qkv[voff + (size_t)nb0 * 192]
                + w1 * g_qkv[voff + (size_t)nb1 * 192]
                + w2 * g_qkv[voff + (size_t)nb2 * 192]
                + w3 * g_qkv[voff + (size_t)nb3 * 192];
        g_o[(size_t)(b * N_ + n) * 64 + h * 16 + lane] = o;
    }
}

// =================== Kernel 4: proj + mask + residual =====================
// 256 threads, 32 rows/block, grid 512. tile = 2 rows x 4 cols.
__global__ __launch_bounds__(256)
void k_proj(const float* __restrict__ x,
            const float* __restrict__ wp, const float* __restrict__ bp)
{
    __shared__ float sw[64 * 64];
    __shared__ float sx[32 * 65];
    __shared__ float sbp[64];
    int tid = threadIdx.x;
    for (int i = tid; i < 1024; i += 256)
        reinterpret_cast<float4*>(sw)[i] = reinterpret_cast<const float4*>(wp)[i];
    if (tid < 64) sbp[tid] = bp[tid];
    int row0 = blockIdx.x * 32;
    for (int i = tid; i < 512; i += 256) {
        float4 v = reinterpret_cast<const float4*>(g_o + (size_t)row0 * 64)[i];
        int r = i >> 4, c = (i & 15) * 4;
        sx[r * 65 + c + 0] = v.x; sx[r * 65 + c + 1] = v.y;
        sx[r * 65 + c + 2] = v.z; sx[r * 65 + c + 3] = v.w;
    }
    __syncthreads();

    int r0 = (tid & 15) * 2;
    int c0 = (tid >> 4) * 4;
    float acc[2][4];
    #pragma unroll
    for (int j = 0; j < 4; j++) { acc[0][j] = sbp[c0 + j]; acc[1][j] = sbp[c0 + j]; }
    #pragma unroll 16
    for (int k = 0; k < 64; k++) {
        float x0 = sx[r0 * 65 + k];
        float x1 = sx[(r0 + 1) * 65 + k];
        float4 wv = *reinterpret_cast<const float4*>(&sw[k * 64 + c0]);
        acc[0][0] += x0 * wv.x; acc[0][1] += x0 * wv.y;
        acc[0][2] += x0 * wv.z; acc[0][3] += x0 * wv.w;
        acc[1][0] += x1 * wv.x; acc[1][1] += x1 * wv.y;
        acc[1][2] += x1 * wv.z; acc[1][3] += x1 * wv.w;
    }
    #pragma unroll
    for (int i = 0; i < 2; i++) {
        int grow = row0 + r0 + i;
        float m = g_mask[grow] ? 0.5f : 0.f;
        float4 xv = *reinterpret_cast<const float4*>(x + (size_t)grow * 64 + c0);
        float4 r;
        r.x = m * acc[i][0] + xv.x; r.y = m * acc[i][1] + xv.y;
        r.z = m * acc[i][2] + xv.z; r.w = m * acc[i][3] + xv.w;
        *reinterpret_cast<float4*>(g_x1 + (size_t)grow * 64 + c0) = r;
    }
}

// ============ Kernel 5: LN2 + MLP (64->256 gelu ->64) + residual ==========
// 512 threads, 32 rows/block, grid 512. gemm1 tile 4x4, gemm2 tile 1x4.
__device__ __forceinline__ float gelu_fast(float v)
{
    float u = v * v;
    float c = 0.7978845608028654f * v * fmaf(0.044715f, u, 1.f);
    float t;
    asm("tanh.approx.f32 %0, %1;" : "=f"(t) : "f"(c));
    return 0.5f * v * (1.f + t);
}

__global__ __launch_bounds__(512, 1)
void k_mlp(const float* __restrict__ g2, const float* __restrict__ b2p,
           const float* __restrict__ w1, const float* __restrict__ bb1,
           const float* __restrict__ w2, const float* __restrict__ bb2,
           float* __restrict__ out)
{
    float* sw1 = dyn_smem;              // [64][256]  = 16384
    float* sw2 = sw1 + 16384;           // [256][64]  = 16384
    float* sx  = sw2 + 16384;           // [32][65]   = 2080
    float* sh  = sx + 2080;             // [32][260]  = 8320
    float* sb1 = sh + 8320;             // 256
    float* sb2 = sb1 + 256;             // 64
    int tid = threadIdx.x;
    for (int i = tid; i < 4096; i += 512) {
        reinterpret_cast<float4*>(sw1)[i] = reinterpret_cast<const float4*>(w1)[i];
        reinterpret_cast<float4*>(sw2)[i] = reinterpret_cast<const float4*>(w2)[i];
    }
    if (tid < 256) sb1[tid] = bb1[tid];
    if (tid < 64)  sb2[tid] = bb2[tid];

    int row0 = blockIdx.x * 32;
    int wid = tid >> 5, lane = tid & 31;
    {   // LN2: half-warp per row
        int r  = 2 * wid + (lane >> 4);
        int c4 = (lane & 15) * 4;
        const float4 xv = *reinterpret_cast<const float4*>(g_x1 + (size_t)(row0 + r) * 64 + c4);
        float s = hsum16(xv.x + xv.y + xv.z + xv.w);
        float mean = s * (1.f / 64.f);
        float d0 = xv.x - mean, d1 = xv.y - mean, d2 = xv.z - mean, d3 = xv.w - mean;
        float vs = hsum16(d0 * d0 + d1 * d1 + d2 * d2 + d3 * d3);
        float inv = rsqrtf(vs * (1.f / 64.f) + 1e-5f);
        sx[r * 65 + c4 + 0] = d0 * inv * g2[c4 + 0] + b2p[c4 + 0];
        sx[r * 65 + c4 + 1] = d1 * inv * g2[c4 + 1] + b2p[c4 + 1];
        sx[r * 65 + c4 + 2] = d2 * inv * g2[c4 + 2] + b2p[c4 + 2];
        sx[r * 65 + c4 + 3] = d3 * inv * g2[c4 + 3] + b2p[c4 + 3];
    }
    __syncthreads();

    // gemm1: 32x256 outputs, 4 rows x 4 cols per thread
    {
        int r0 = (tid & 7) * 4;
        int c0 = (tid >> 3) * 4;
        float acc[4][4];
        #pragma unroll
        for (int i = 0; i < 4; i++)
            #pragma unroll
            for (int j = 0; j < 4; j++) acc[i][j] = sb1[c0 + j];
        #pragma unroll 8
        for (int k = 0; k < 64; k++) {
            float xr0 = sx[(r0 + 0) * 65 + k];
            float xr1 = sx[(r0 + 1) * 65 + k];
            float xr2 = sx[(r0 + 2) * 65 + k];
            float xr3 = sx[(r0 + 3) * 65 + k];
            float4 wv = *reinterpret_cast<const float4*>(&sw1[k * 256 + c0]);
            acc[0][0] += xr0 * wv.x; acc[0][1] += xr0 * wv.y; acc[0][2] += xr0 * wv.z; acc[0][3] += xr0 * wv.w;
            acc[1][0] += xr1 * wv.x; acc[1][1] += xr1 * wv.y; acc[1][2] += xr1 * wv.z; acc[1][3] += xr1 * wv.w;
            acc[2][0] += xr2 * wv.x; acc[2][1] += xr2 * wv.y; acc[2][2] += xr2 * wv.z; acc[2][3] += xr2 * wv.w;
            acc[3][0] += xr3 * wv.x; acc[3][1] += xr3 * wv.y; acc[3][2] += xr3 * wv.z; acc[3][3] += xr3 * wv.w;
        }
        #pragma unroll
        for (int i = 0; i < 4; i++) {
            float4 hv;
            hv.x = gelu_fast(acc[i][0]); hv.y = gelu_fast(acc[i][1]);
            hv.z = gelu_fast(acc[i][2]); hv.w = gelu_fast(acc[i][3]);
            *reinterpret_cast<float4*>(&sh[(r0 + i) * 260 + c0]) = hv;
        }
    }
    __syncthreads();

    // gemm2: 32x64 outputs, 1 row x 4 cols per thread
    {
        int r  = tid >> 4;
        int c0 = (tid & 15) * 4;
        float a0 = sb2[c0 + 0], a1 = sb2[c0 + 1], a2 = sb2[c0 + 2], a3 = sb2[c0 + 3];
        const float* hr = &sh[r * 260];
        #pragma unroll 8
        for (int k = 0; k < 256; k++) {
            float hv = hr[k];
            float4 wv = *reinterpret_cast<const float4*>(&sw2[k * 64 + c0]);
            a0 += hv * wv.x; a1 += hv * wv.y; a2 += hv * wv.z; a3 += hv * wv.w;
        }
        size_t gbase = (size_t)(row0 + r) * 64 + c0;
        float4 xv = *reinterpret_cast<const float4*>(g_x1 + gbase);
        float4 rr;
        rr.x = 0.5f * a0 + xv.x; rr.y = 0.5f * a1 + xv.y;
        rr.z = 0.5f * a2 + xv.z; rr.w = 0.5f * a3 + xv.w;
        *reinterpret_cast<float4*>(out + gbase) = rr;
    }
}

// ============================== launcher ==================================
extern "C" void kernel_launch(void* const* d_in, const int* in_sizes, int n_in,
                              void* d_out, int out_size)
{
    const float* x      = (const float*)d_in[0];
    const float* coords = (const float*)d_in[1];
    const unsigned char* mask_raw = (const unsigned char*)d_in[2];
    const float* ln1g = (const float*)d_in[3];
    const float* ln1b = (const float*)d_in[4];
    const float* ln2g = (const float*)d_in[5];
    const float* ln2b = (const float*)d_in[6];
    const float* wqkv = (const float*)d_in[7];
    const float* bqkv = (const float*)d_in[8];
    const float* wproj = (const float*)d_in[9];
    const float* bproj = (const float*)d_in[10];
    const float* w1 = (const float*)d_in[11];
    const float* b1 = (const float*)d_in[12];
    const float* w2 = (const float*)d_in[13];
    const float* b2 = (const float*)d_in[14];
    float* out = (float*)d_out;

    static bool attr_done = false;
    if (!attr_done) {
        cudaFuncSetAttribute(k_ln_qkv, cudaFuncAttributeMaxDynamicSharedMemorySize, 60 * 1024);
        cudaFuncSetAttribute(k_knn,    cudaFuncAttributeMaxDynamicSharedMemorySize, 66 * 1024);
        cudaFuncSetAttribute(k_mlp,    cudaFuncAttributeMaxDynamicSharedMemorySize, 176 * 1024);
        attr_done = true;
    }

    k_maskfix<<<1, 1024>>>(mask_raw);

    size_t smem_qkv = (12288 + 2080 + 192) * sizeof(float);
    k_ln_qkv<<<ROWS_ / 32, 512, smem_qkv>>>(x, ln1g, ln1b, wqkv, bqkv);

    size_t smem_knn = (size_t)N_ * sizeof(float4);
    k_knn<<<B_ * (N_ / 16), 512, smem_knn>>>(coords);

    k_attn<<<(ROWS_ * H_) / 8, 256>>>();

    k_proj<<<ROWS_ / 32, 256>>>(x, wproj, bproj);

    size_t smem_mlp = (16384 + 16384 + 2080 + 8320 + 256 + 64) * sizeof(float);
    k_mlp<<<ROWS_ / 32, 512, smem_mlp>>>(ln2g, ln2b, w1, b1, w2, b2, out);
}

// round 11
// speedup vs baseline: 4.6703x; 1.9210x over previous
#include <cuda_runtime.h>
#include <cuda_bf16.h>
#include <cstdint>

#define B_ 4
#define N_ 4096
#define C_ 64
#define H_ 4
#define DH_ 16
#define M_ 256
#define KNN_ 10
#define KS_ 4
#define ROWS_ (B_ * N_)   // 16384

typedef unsigned long long u64;
typedef unsigned int u32;

// ---------------- scratch (device globals; no runtime alloc allowed) ------
__device__ float g_qkv[ROWS_ * 3 * C_];   // [B,N,3C] : q|k|v per row
__device__ int   g_nbr[ROWS_ * KNN_];     // [B,N,10]
__device__ float g_o  [ROWS_ * C_];       // attention output (pre-proj)
__device__ float g_x1 [ROWS_ * C_];       // residual after attn
__device__ unsigned char g_mask[ROWS_];   // canonical 0/1 mask

extern __shared__ float dyn_smem[];

// ---------------- f32x2 packed helpers (sm_103a) --------------------------
__device__ __forceinline__ u64 f2x_add(u64 a, u64 b)
{ u64 r; asm("add.rn.f32x2 %0,%1,%2;" : "=l"(r) : "l"(a), "l"(b)); return r; }
__device__ __forceinline__ u64 f2x_mul(u64 a, u64 b)
{ u64 r; asm("mul.rn.f32x2 %0,%1,%2;" : "=l"(r) : "l"(a), "l"(b)); return r; }
__device__ __forceinline__ u64 f2x_fma(u64 a, u64 b, u64 c)
{ u64 r; asm("fma.rn.f32x2 %0,%1,%2,%3;" : "=l"(r) : "l"(a), "l"(b), "l"(c)); return r; }
__device__ __forceinline__ u64 f2x_pack(float lo, float hi)
{ u64 r; asm("mov.b64 %0,{%1,%2};" : "=l"(r) : "f"(lo), "f"(hi)); return r; }
__device__ __forceinline__ void f2x_unpack(float& lo, float& hi, u64 v)
{ asm("mov.b64 {%0,%1},%2;" : "=f"(lo), "=f"(hi) : "l"(v)); }

// ================= Kernel 0: normalize mask dtype =========================
// Harness transports the bool mask as int32/float32 (or uint8). Every block
// detects the layout from the first 16KB (all blocks agree), then writes its
// 1024-element slice of the canonical byte mask. 16 blocks x 1024 threads.
__global__ void k_maskfix(const unsigned char* __restrict__ raw)
{
    __shared__ int s_bytes;
    int tid = threadIdx.x;
    if (tid == 0) s_bytes = 0;
    __syncthreads();
    const u32* w = reinterpret_cast<const u32*>(raw);
    int bad = 0;
    #pragma unroll
    for (int i = 0; i < 4; i++) {
        u32 v = w[tid + 1024 * i];
        if (v != 0u && v != 1u && v != 0x3f800000u) bad = 1;
    }
    if (bad) s_bytes = 1;
    __syncthreads();
    int idx = blockIdx.x * 1024 + tid;
    if (s_bytes) g_mask[idx] = raw[idx] ? 1 : 0;
    else         g_mask[idx] = (w[idx] != 0u) ? 1 : 0;
}

// -------- helper: 16-lane reduction (half-warp, xor offsets < 16) ---------
__device__ __forceinline__ float hsum16(float s)
{
    s += __shfl_xor_sync(0xffffffffu, s, 8);
    s += __shfl_xor_sync(0xffffffffu, s, 4);
    s += __shfl_xor_sync(0xffffffffu, s, 2);
    s += __shfl_xor_sync(0xffffffffu, s, 1);
    return s;
}

// ======================= Kernel 1: LN1 + QKV GEMM =========================
__global__ __launch_bounds__(512, 1)
void k_ln_qkv(const float* __restrict__ x,
              const float* __restrict__ g1, const float* __restrict__ b1,
              const float* __restrict__ wqkv, const float* __restrict__ bqkv)
{
    float* sw = dyn_smem;            // [64][192]
    float* sx = sw + 12288;          // [32][65]
    float* sb = sx + 2080;           // 192
    int tid = threadIdx.x;
    for (int i = tid; i < 12288 / 4; i += 512)
        reinterpret_cast<float4*>(sw)[i] = reinterpret_cast<const float4*>(wqkv)[i];
    if (tid < 192) sb[tid] = bqkv[tid];

    int row0 = blockIdx.x * 32;
    int wid = tid >> 5, lane = tid & 31;
    {
        int r  = 2 * wid + (lane >> 4);
        int c4 = (lane & 15) * 4;
        const float4 xv = *reinterpret_cast<const float4*>(x + (size_t)(row0 + r) * 64 + c4);
        float s = hsum16(xv.x + xv.y + xv.z + xv.w);
        float mean = s * (1.f / 64.f);
        float d0 = xv.x - mean, d1 = xv.y - mean, d2 = xv.z - mean, d3 = xv.w - mean;
        float vs = hsum16(d0 * d0 + d1 * d1 + d2 * d2 + d3 * d3);
        float inv = rsqrtf(vs * (1.f / 64.f) + 1e-5f);
        sx[r * 65 + c4 + 0] = d0 * inv * g1[c4 + 0] + b1[c4 + 0];
        sx[r * 65 + c4 + 1] = d1 * inv * g1[c4 + 1] + b1[c4 + 1];
        sx[r * 65 + c4 + 2] = d2 * inv * g1[c4 + 2] + b1[c4 + 2];
        sx[r * 65 + c4 + 3] = d3 * inv * g1[c4 + 3] + b1[c4 + 3];
    }
    __syncthreads();

    int r0 = (tid & 15) * 2;
    int c0 = (tid >> 4) * 6;
    float acc[2][6];
    #pragma unroll
    for (int j = 0; j < 6; j++) { acc[0][j] = sb[c0 + j]; acc[1][j] = sb[c0 + j]; }
    #pragma unroll 16
    for (int k = 0; k < 64; k++) {
        float x0 = sx[r0 * 65 + k];
        float x1 = sx[(r0 + 1) * 65 + k];
        const float* wr = &sw[k * 192 + c0];
        float2 w0 = *reinterpret_cast<const float2*>(wr);
        float2 w1 = *reinterpret_cast<const float2*>(wr + 2);
        float2 w2 = *reinterpret_cast<const float2*>(wr + 4);
        acc[0][0] += x0 * w0.x; acc[0][1] += x0 * w0.y;
        acc[0][2] += x0 * w1.x; acc[0][3] += x0 * w1.y;
        acc[0][4] += x0 * w2.x; acc[0][5] += x0 * w2.y;
        acc[1][0] += x1 * w0.x; acc[1][1] += x1 * w0.y;
        acc[1][2] += x1 * w1.x; acc[1][3] += x1 * w1.y;
        acc[1][4] += x1 * w2.x; acc[1][5] += x1 * w2.y;
    }
    #pragma unroll
    for (int i = 0; i < 2; i++) {
        float* outp = g_qkv + (size_t)(row0 + r0 + i) * 192 + c0;
        #pragma unroll
        for (int j = 0; j < 6; j++) outp[j] = acc[i][j];
    }
}

// ======================= Kernel 2: KNN (packed, buffered) =================
// 512 threads = 16 warps; warp handles 2 queries; block covers 32 queries.
// Coords stored NEGATED (and masked-shifted) planar in smem, so q - p is one
// packed add; 2 candidates/lane/iter via f32x2.
// Pass A: per-lane min over its 128 candidates -> T = 10th-smallest of 32
// lane minima (>= true 10th distance). Pass B: candidates with d2 <= T pushed
// to a per-query smem buffer (expected ~15, cap 64). Exact top-10 selected by
// REDUX min rounds with (d2, idx) lexicographic tie-break (matches JAX).
__global__ __launch_bounds__(512)
void k_knn(const float* __restrict__ coords)
{
    float* snx = dyn_smem;
    float* sny = snx + N_;
    float* snz = sny + N_;
    uint2* sbuf = reinterpret_cast<uint2*>(snz + N_);   // [32][64]
    int*   scnt = reinterpret_cast<int*>(sbuf + 32 * 64);

    int b    = blockIdx.x >> 7;          // 128 tiles per batch
    int tile = blockIdx.x & 127;
    int tid = threadIdx.x;
    const float* cb = coords + (size_t)b * N_ * 3;
    const unsigned char* mb = g_mask + (size_t)b * N_;
    for (int i = tid; i < N_; i += 512) {
        float cx = cb[3 * i], cy = cb[3 * i + 1], cz = cb[3 * i + 2];
        if (!mb[i]) cx += 1e5f;          // masked pushed far (d2 ~1e10 >> 768)
        snx[i] = -cx; sny[i] = -cy; snz[i] = -cz;
    }
    __syncthreads();

    int wid = tid >> 5, lane = tid & 31;
    int n0 = tile * 32 + wid * 2;        // queries n0, n0+1

    float q0x = -snx[n0],     q0y = -sny[n0],     q0z = -snz[n0];
    float q1x = -snx[n0 + 1], q1y = -sny[n0 + 1], q1z = -snz[n0 + 1];
    u64 q0x2 = f2x_pack(q0x, q0x), q0y2 = f2x_pack(q0y, q0y), q0z2 = f2x_pack(q0z, q0z);
    u64 q1x2 = f2x_pack(q1x, q1x), q1y2 = f2x_pack(q1y, q1y), q1z2 = f2x_pack(q1z, q1z);

    // ---- pass A: per-lane minima (candidates j2 = t*64 + lane*2, +1)
    float mA0 = 3.4e38f, mA1 = 3.4e38f;
    #pragma unroll 4
    for (int t = 0; t < 64; t++) {
        int j2 = t * 64 + lane * 2;
        u64 nx2 = *reinterpret_cast<const u64*>(snx + j2);
        u64 ny2 = *reinterpret_cast<const u64*>(sny + j2);
        u64 nz2 = *reinterpret_cast<const u64*>(snz + j2);
        {
            u64 dx = f2x_add(q0x2, nx2), dy = f2x_add(q0y2, ny2), dz = f2x_add(q0z2, nz2);
            u64 s2 = f2x_fma(dx, dx, f2x_fma(dy, dy, f2x_mul(dz, dz)));
            float da, db; f2x_unpack(da, db, s2);
            mA0 = fminf(mA0, fminf(da, db));
        }
        {
            u64 dx = f2x_add(q1x2, nx2), dy = f2x_add(q1y2, ny2), dz = f2x_add(q1z2, nz2);
            u64 s2 = f2x_fma(dx, dx, f2x_fma(dy, dy, f2x_mul(dz, dz)));
            float da, db; f2x_unpack(da, db, s2);
            mA1 = fminf(mA1, fminf(da, db));
        }
    }

    // ---- T = 10th smallest of 32 lane minima (u32-order = float order >=0)
    u32 T0, T1;
    {
        u32 cur = __float_as_uint(mA0), mv = 0;
        #pragma unroll
        for (int r = 0; r < KNN_; r++) {
            mv = __reduce_min_sync(0xffffffffu, cur);
            u32 bal = __ballot_sync(0xffffffffu, cur == mv);
            if (lane == __ffs(bal) - 1) cur = 0xffffffffu;
        }
        T0 = mv;
    }
    {
        u32 cur = __float_as_uint(mA1), mv = 0;
        #pragma unroll
        for (int r = 0; r < KNN_; r++) {
            mv = __reduce_min_sync(0xffffffffu, cur);
            u32 bal = __ballot_sync(0xffffffffu, cur == mv);
            if (lane == __ffs(bal) - 1) cur = 0xffffffffu;
        }
        T1 = mv;
    }

    int slot0 = wid * 2, slot1 = wid * 2 + 1;
    if (lane < 2) scnt[wid * 2 + lane] = 0;
    __syncwarp();

    // ---- pass B: push candidates with d2 <= T
    #pragma unroll 2
    for (int t = 0; t < 64; t++) {
        int j2 = t * 64 + lane * 2;
        u64 nx2 = *reinterpret_cast<const u64*>(snx + j2);
        u64 ny2 = *reinterpret_cast<const u64*>(sny + j2);
        u64 nz2 = *reinterpret_cast<const u64*>(snz + j2);
        u64 dx0 = f2x_add(q0x2, nx2), dy0 = f2x_add(q0y2, ny2), dz0 = f2x_add(q0z2, nz2);
        u64 s20 = f2x_fma(dx0, dx0, f2x_fma(dy0, dy0, f2x_mul(dz0, dz0)));
        u64 dx1 = f2x_add(q1x2, nx2), dy1 = f2x_add(q1y2, ny2), dz1 = f2x_add(q1z2, nz2);
        u64 s21 = f2x_fma(dx1, dx1, f2x_fma(dy1, dy1, f2x_mul(dz1, dz1)));
        float a0, b0, a1, b1;
        f2x_unpack(a0, b0, s20);
        f2x_unpack(a1, b1, s21);
        u32 ba0 = __float_as_uint(a0), bb0 = __float_as_uint(b0);
        u32 ba1 = __float_as_uint(a1), bb1 = __float_as_uint(b1);
        bool h00 = ba0 <= T0, h01 = bb0 <= T0;
        bool h10 = ba1 <= T1, h11 = bb1 <= T1;
        if (__any_sync(0xffffffffu, h00 | h01 | h10 | h11)) {
            if (h00) { int p = atomicAdd(&scnt[slot0], 1); if (p < 64) sbuf[slot0 * 64 + p] = make_uint2(ba0, (u32)j2); }
            if (h01) { int p = atomicAdd(&scnt[slot0], 1); if (p < 64) sbuf[slot0 * 64 + p] = make_uint2(bb0, (u32)(j2 + 1)); }
            if (h10) { int p = atomicAdd(&scnt[slot1], 1); if (p < 64) sbuf[slot1 * 64 + p] = make_uint2(ba1, (u32)j2); }
            if (h11) { int p = atomicAdd(&scnt[slot1], 1); if (p < 64) sbuf[slot1 * 64 + p] = make_uint2(bb1, (u32)(j2 + 1)); }
        }
    }
    __syncwarp();

    // ---- exact top-10 per query (stable by (d2, idx))
    #pragma unroll
    for (int q = 0; q < 2; q++) {
        int slot = wid * 2 + q;
        int c = scnt[slot]; if (c > 64) c = 64;
        uint2 e0 = (lane      < c) ? sbuf[slot * 64 + lane]      : make_uint2(0xffffffffu, 0xffffffffu);
        uint2 e1 = (lane + 32 < c) ? sbuf[slot * 64 + lane + 32] : make_uint2(0xffffffffu, 0xffffffffu);
        int* outp = g_nbr + ((size_t)b * N_ + n0 + q) * KNN_;
        #pragma unroll
        for (int r = 0; r < KNN_; r++) {
            u32 mv = __reduce_min_sync(0xffffffffu, e0.x < e1.x ? e0.x : e1.x);
            u32 ci = 0xffffffffu;
            if (e0.x == mv) ci = e0.y;
            if (e1.x == mv && e1.y < ci) ci = e1.y;
            u32 mi = __reduce_min_sync(0xffffffffu, ci);
            if (lane == 0) outp[r] = (int)mi;
            if (e0.x == mv && e0.y == mi) e0.x = 0xffffffffu;
            else if (e1.x == mv && e1.y == mi) e1.x = 0xffffffffu;
        }
    }
}

// =================== Kernel 3: sparse dynamic attention ===================
// warp per (b,n,h). q via broadcast LDG (no shuffles); stable top-4 via
// REDUX max on order-preserving u32 bits (tie -> lowest lane = smallest k).
__global__ void k_attn()
{
    int g = blockIdx.x * 8 + (threadIdx.x >> 5);
    int lane = threadIdx.x & 31;
    int h = g & 3;
    int n = (g >> 2) & (N_ - 1);
    int b = g >> 14;
    size_t row = (size_t)(b * N_ + n);

    int nbrj = 0;
    float s = 0.f;
    u32 ub = 0;
    if (lane < KNN_) {
        nbrj = g_nbr[row * KNN_ + lane];
        const float4* kr = reinterpret_cast<const float4*>(
            g_qkv + ((size_t)b * N_ + nbrj) * 192 + 64 + h * 16);
        const float4* qr = reinterpret_cast<const float4*>(g_qkv + row * 192 + h * 16);
        float4 k0 = kr[0], k1 = kr[1], k2 = kr[2], k3 = kr[3];
        float4 q0 = qr[0], q1 = qr[1], q2 = qr[2], q3 = qr[3];
        float acc = q0.x * k0.x;
        acc = fmaf(q0.y, k0.y, acc); acc = fmaf(q0.z, k0.z, acc); acc = fmaf(q0.w, k0.w, acc);
        acc = fmaf(q1.x, k1.x, acc); acc = fmaf(q1.y, k1.y, acc); acc = fmaf(q1.z, k1.z, acc); acc = fmaf(q1.w, k1.w, acc);
        acc = fmaf(q2.x, k2.x, acc); acc = fmaf(q2.y, k2.y, acc); acc = fmaf(q2.z, k2.z, acc); acc = fmaf(q2.w, k2.w, acc);
        acc = fmaf(q3.x, k3.x, acc); acc = fmaf(q3.y, k3.y, acc); acc = fmaf(q3.z, k3.z, acc); acc = fmaf(q3.w, k3.w, acc);
        s = acc * 0.25f;                     // 1/sqrt(16)
        if (!g_mask[b * N_ + nbrj]) s -= 1e9f;
        u32 bits = __float_as_uint(s);
        ub = (s >= 0.f) ? (bits | 0x80000000u) : ~bits;   // >0 always
    }

    u32 cur = ub;
    float w[KS_]; int nb[KS_];
    float mx = 0.f;
    #pragma unroll
    for (int r = 0; r < KS_; r++) {
        u32 mv = __reduce_max_sync(0xffffffffu, cur);
        u32 bal = __ballot_sync(0xffffffffu, cur == mv);
        int mi = __ffs(bal) - 1;
        float sv = __shfl_sync(0xffffffffu, s, mi);
        if (r == 0) mx = sv;
        w[r] = __expf(sv - mx);
        nb[r] = __shfl_sync(0xffffffffu, nbrj, mi);
        if (lane == mi) cur = 0;
    }
    float inv = 1.f / (w[0] + w[1] + w[2] + w[3]);

    if (lane < 16) {
        size_t voff = (size_t)b * N_ * 192 + 128 + h * 16 + lane;
        float o = w[0] * g_qkv[voff + (size_t)nb[0] * 192]
                + w[1] * g_qkv[voff + (size_t)nb[1] * 192]
                + w[2] * g_qkv[voff + (size_t)nb[2] * 192]
                + w[3] * g_qkv[voff + (size_t)nb[3] * 192];
        g_o[row * 64 + h * 16 + lane] = o * inv;
    }
}

// =================== Kernel 4: proj + mask + residual =====================
__global__ __launch_bounds__(256)
void k_proj(const float* __restrict__ x,
            const float* __restrict__ wp, const float* __restrict__ bp)
{
    __shared__ float sw[64 * 64];
    __shared__ float sx[32 * 65];
    __shared__ float sbp[64];
    int tid = threadIdx.x;
    for (int i = tid; i < 1024; i += 256)
        reinterpret_cast<float4*>(sw)[i] = reinterpret_cast<const float4*>(wp)[i];
    if (tid < 64) sbp[tid] = bp[tid];
    int row0 = blockIdx.x * 32;
    for (int i = tid; i < 512; i += 256) {
        float4 v = reinterpret_cast<const float4*>(g_o + (size_t)row0 * 64)[i];
        int r = i >> 4, c = (i & 15) * 4;
        sx[r * 65 + c + 0] = v.x; sx[r * 65 + c + 1] = v.y;
        sx[r * 65 + c + 2] = v.z; sx[r * 65 + c + 3] = v.w;
    }
    __syncthreads();

    int r0 = (tid & 15) * 2;
    int c0 = (tid >> 4) * 4;
    float acc[2][4];
    #pragma unroll
    for (int j = 0; j < 4; j++) { acc[0][j] = sbp[c0 + j]; acc[1][j] = sbp[c0 + j]; }
    #pragma unroll 16
    for (int k = 0; k < 64; k++) {
        float x0 = sx[r0 * 65 + k];
        float x1 = sx[(r0 + 1) * 65 + k];
        float4 wv = *reinterpret_cast<const float4*>(&sw[k * 64 + c0]);
        acc[0][0] += x0 * wv.x; acc[0][1] += x0 * wv.y;
        acc[0][2] += x0 * wv.z; acc[0][3] += x0 * wv.w;
        acc[1][0] += x1 * wv.x; acc[1][1] += x1 * wv.y;
        acc[1][2] += x1 * wv.z; acc[1][3] += x1 * wv.w;
    }
    #pragma unroll
    for (int i = 0; i < 2; i++) {
        int grow = row0 + r0 + i;
        float m = g_mask[grow] ? 0.5f : 0.f;
        float4 xv = *reinterpret_cast<const float4*>(x + (size_t)grow * 64 + c0);
        float4 r;
        r.x = m * acc[i][0] + xv.x; r.y = m * acc[i][1] + xv.y;
        r.z = m * acc[i][2] + xv.z; r.w = m * acc[i][3] + xv.w;
        *reinterpret_cast<float4*>(g_x1 + (size_t)grow * 64 + c0) = r;
    }
}

// ============ Kernel 5: LN2 + MLP (persistent; weights loaded once) =======
__device__ __forceinline__ float gelu_fast(float v)
{
    float u = v * v;
    float c = 0.7978845608028654f * v * fmaf(0.044715f, u, 1.f);
    float t;
    asm("tanh.approx.f32 %0, %1;" : "=f"(t) : "f"(c));
    return 0.5f * v * (1.f + t);
}

__global__ __launch_bounds__(512, 1)
void k_mlp(const float* __restrict__ g2, const float* __restrict__ b2p,
           const float* __restrict__ w1, const float* __restrict__ bb1,
           const float* __restrict__ w2, const float* __restrict__ bb2,
           float* __restrict__ out)
{
    float* sw1 = dyn_smem;              // [64][256]
    float* sw2 = sw1 + 16384;           // [256][64]
    float* sx  = sw2 + 16384;           // [32][65]
    float* sh  = sx + 2080;             // [32][260]
    float* sb1 = sh + 8320;             // 256
    float* sb2 = sb1 + 256;             // 64
    int tid = threadIdx.x;
    for (int i = tid; i < 4096; i += 512) {
        reinterpret_cast<float4*>(sw1)[i] = reinterpret_cast<const float4*>(w1)[i];
        reinterpret_cast<float4*>(sw2)[i] = reinterpret_cast<const float4*>(w2)[i];
    }
    if (tid < 256) sb1[tid] = bb1[tid];
    if (tid < 64)  sb2[tid] = bb2[tid];
    __syncthreads();

    int wid = tid >> 5, lane = tid & 31;

    for (int tile = blockIdx.x; tile < ROWS_ / 32; tile += 148) {
        int row0 = tile * 32;
        {   // LN2: half-warp per row
            int r  = 2 * wid + (lane >> 4);
            int c4 = (lane & 15) * 4;
            const float4 xv = *reinterpret_cast<const float4*>(g_x1 + (size_t)(row0 + r) * 64 + c4);
            float s = hsum16(xv.x + xv.y + xv.z + xv.w);
            float mean = s * (1.f / 64.f);
            float d0 = xv.x - mean, d1 = xv.y - mean, d2 = xv.z - mean, d3 = xv.w - mean;
            float vs = hsum16(d0 * d0 + d1 * d1 + d2 * d2 + d3 * d3);
            float inv = rsqrtf(vs * (1.f / 64.f) + 1e-5f);
            sx[r * 65 + c4 + 0] = d0 * inv * g2[c4 + 0] + b2p[c4 + 0];
            sx[r * 65 + c4 + 1] = d1 * inv * g2[c4 + 1] + b2p[c4 + 1];
            sx[r * 65 + c4 + 2] = d2 * inv * g2[c4 + 2] + b2p[c4 + 2];
            sx[r * 65 + c4 + 3] = d3 * inv * g2[c4 + 3] + b2p[c4 + 3];
        }
        __syncthreads();

        // gemm1: 32x256, 4 rows x 4 cols per thread
        {
            int r0 = (tid & 7) * 4;
            int c0 = (tid >> 3) * 4;
            float acc[4][4];
            #pragma unroll
            for (int i = 0; i < 4; i++)
                #pragma unroll
                for (int j = 0; j < 4; j++) acc[i][j] = sb1[c0 + j];
            #pragma unroll 8
            for (int k = 0; k < 64; k++) {
                float xr0 = sx[(r0 + 0) * 65 + k];
                float xr1 = sx[(r0 + 1) * 65 + k];
                float xr2 = sx[(r0 + 2) * 65 + k];
                float xr3 = sx[(r0 + 3) * 65 + k];
                float4 wv = *reinterpret_cast<const float4*>(&sw1[k * 256 + c0]);
                acc[0][0] += xr0 * wv.x; acc[0][1] += xr0 * wv.y; acc[0][2] += xr0 * wv.z; acc[0][3] += xr0 * wv.w;
                acc[1][0] += xr1 * wv.x; acc[1][1] += xr1 * wv.y; acc[1][2] += xr1 * wv.z; acc[1][3] += xr1 * wv.w;
                acc[2][0] += xr2 * wv.x; acc[2][1] += xr2 * wv.y; acc[2][2] += xr2 * wv.z; acc[2][3] += xr2 * wv.w;
                acc[3][0] += xr3 * wv.x; acc[3][1] += xr3 * wv.y; acc[3][2] += xr3 * wv.z; acc[3][3] += xr3 * wv.w;
            }
            #pragma unroll
            for (int i = 0; i < 4; i++) {
                float4 hv;
                hv.x = gelu_fast(acc[i][0]); hv.y = gelu_fast(acc[i][1]);
                hv.z = gelu_fast(acc[i][2]); hv.w = gelu_fast(acc[i][3]);
                *reinterpret_cast<float4*>(&sh[(r0 + i) * 260 + c0]) = hv;
            }
        }
        __syncthreads();

        // gemm2: 32x64, 1 row x 4 cols per thread
        {
            int r  = tid >> 4;
            int c0 = (tid & 15) * 4;
            float a0 = sb2[c0 + 0], a1 = sb2[c0 + 1], a2 = sb2[c0 + 2], a3 = sb2[c0 + 3];
            const float* hr = &sh[r * 260];
            #pragma unroll 8
            for (int k = 0; k < 256; k++) {
                float hv = hr[k];
                float4 wv = *reinterpret_cast<const float4*>(&sw2[k * 64 + c0]);
                a0 += hv * wv.x; a1 += hv * wv.y; a2 += hv * wv.z; a3 += hv * wv.w;
            }
            size_t gbase = (size_t)(row0 + r) * 64 + c0;
            float4 xv = *reinterpret_cast<const float4*>(g_x1 + gbase);
            float4 rr;
            rr.x = 0.5f * a0 + xv.x; rr.y = 0.5f * a1 + xv.y;
            rr.z = 0.5f * a2 + xv.z; rr.w = 0.5f * a3 + xv.w;
            *reinterpret_cast<float4*>(out + gbase) = rr;
        }
        __syncthreads();
    }
}

// ============================== launcher ==================================
extern "C" void kernel_launch(void* const* d_in, const int* in_sizes, int n_in,
                              void* d_out, int out_size)
{
    const float* x      = (const float*)d_in[0];
    const float* coords = (const float*)d_in[1];
    const unsigned char* mask_raw = (const unsigned char*)d_in[2];
    const float* ln1g = (const float*)d_in[3];
    const float* ln1b = (const float*)d_in[4];
    const float* ln2g = (const float*)d_in[5];
    const float* ln2b = (const float*)d_in[6];
    const float* wqkv = (const float*)d_in[7];
    const float* bqkv = (const float*)d_in[8];
    const float* wproj = (const float*)d_in[9];
    const float* bproj = (const float*)d_in[10];
    const float* w1 = (const float*)d_in[11];
    const float* b1 = (const float*)d_in[12];
    const float* w2 = (const float*)d_in[13];
    const float* b2 = (const float*)d_in[14];
    float* out = (float*)d_out;

    static bool attr_done = false;
    if (!attr_done) {
        cudaFuncSetAttribute(k_ln_qkv, cudaFuncAttributeMaxDynamicSharedMemorySize, 60 * 1024);
        cudaFuncSetAttribute(k_knn,    cudaFuncAttributeMaxDynamicSharedMemorySize, 68 * 1024);
        cudaFuncSetAttribute(k_mlp,    cudaFuncAttributeMaxDynamicSharedMemorySize, 176 * 1024);
        attr_done = true;
    }

    k_maskfix<<<16, 1024>>>(mask_raw);

    size_t smem_qkv = (12288 + 2080 + 192) * sizeof(float);
    k_ln_qkv<<<ROWS_ / 32, 512, smem_qkv>>>(x, ln1g, ln1b, wqkv, bqkv);

    size_t smem_knn = 3 * N_ * sizeof(float) + 32 * 64 * sizeof(uint2) + 32 * sizeof(int);
    k_knn<<<B_ * (N_ / 32), 512, smem_knn>>>(coords);

    k_attn<<<(ROWS_ * H_) / 8, 256>>>();

    k_proj<<<ROWS_ / 32, 256>>>(x, wproj, bproj);

    size_t smem_mlp = (16384 + 16384 + 2080 + 8320 + 256 + 64) * sizeof(float);
    k_mlp<<<148, 512, smem_mlp>>>(ln2g, ln2b, w1, b1, w2, b2, out);
}

// round 14
// speedup vs baseline: 5.6299x; 1.2055x over previous
#include <cuda_runtime.h>
#include <cuda_bf16.h>
#include <cstdint>

#define B_ 4
#define N_ 4096
#define C_ 64
#define H_ 4
#define DH_ 16
#define M_ 256
#define KNN_ 10
#define KS_ 4
#define ROWS_ (B_ * N_)   // 16384

typedef unsigned long long u64;
typedef unsigned int u32;

// ---------------- scratch (device globals; no runtime alloc allowed) ------
__device__ float g_qkv[ROWS_ * 3 * C_];   // [B,N,3C] : q|k|v per row
__device__ int   g_nbr[ROWS_ * KNN_];     // [B,N,10]
__device__ float g_x1 [ROWS_ * C_];       // residual after attn+proj

extern __shared__ float dyn_smem[];

// ---------------- f32x2 packed helpers (sm_103a) --------------------------
__device__ __forceinline__ u64 f2x_add(u64 a, u64 b)
{ u64 r; asm("add.rn.f32x2 %0,%1,%2;" : "=l"(r) : "l"(a), "l"(b)); return r; }
__device__ __forceinline__ u64 f2x_mul(u64 a, u64 b)
{ u64 r; asm("mul.rn.f32x2 %0,%1,%2;" : "=l"(r) : "l"(a), "l"(b)); return r; }
__device__ __forceinline__ u64 f2x_fma(u64 a, u64 b, u64 c)
{ u64 r; asm("fma.rn.f32x2 %0,%1,%2,%3;" : "=l"(r) : "l"(a), "l"(b), "l"(c)); return r; }
__device__ __forceinline__ u64 f2x_pack(float lo, float hi)
{ u64 r; asm("mov.b64 %0,{%1,%2};" : "=l"(r) : "f"(lo), "f"(hi)); return r; }
__device__ __forceinline__ void f2x_unpack(float& lo, float& hi, u64 v)
{ asm("mov.b64 {%0,%1},%2;" : "=f"(lo), "=f"(hi) : "l"(v)); }

// -------- helper: 16-lane reduction (half-warp, xor offsets < 16) ---------
__device__ __forceinline__ float hsum16(float s)
{
    s += __shfl_xor_sync(0xffffffffu, s, 8);
    s += __shfl_xor_sync(0xffffffffu, s, 4);
    s += __shfl_xor_sync(0xffffffffu, s, 2);
    s += __shfl_xor_sync(0xffffffffu, s, 1);
    return s;
}

// ================== Kernel A: fat front (LN1+QKV | KNN) ===================
// blocks [0,512): LN1 + QKV GEMM (f32x2, 32 rows/block)
// blocks [512,1024): KNN (two-pass thresholded, 32 queries/block)
// Mask is transported as 4-byte words (established R7 vs R8): read u32 != 0.

__device__ __forceinline__ void qkv_body(
    int bidx, const float* __restrict__ x,
    const float* __restrict__ g1, const float* __restrict__ b1,
    const float* __restrict__ wqkv, const float* __restrict__ bqkv)
{
    float* sw = dyn_smem;            // [64][192]
    float* sx = sw + 12288;          // [32][65]
    float* sb = sx + 2080;           // 192
    int tid = threadIdx.x;
    for (int i = tid; i < 12288 / 4; i += 512)
        reinterpret_cast<float4*>(sw)[i] = reinterpret_cast<const float4*>(wqkv)[i];
    if (tid < 192) sb[tid] = bqkv[tid];

    int row0 = bidx * 32;
    int wid = tid >> 5, lane = tid & 31;
    {
        int r  = 2 * wid + (lane >> 4);
        int c4 = (lane & 15) * 4;
        const float4 xv = *reinterpret_cast<const float4*>(x + (size_t)(row0 + r) * 64 + c4);
        float s = hsum16(xv.x + xv.y + xv.z + xv.w);
        float mean = s * (1.f / 64.f);
        float d0 = xv.x - mean, d1 = xv.y - mean, d2 = xv.z - mean, d3 = xv.w - mean;
        float vs = hsum16(d0 * d0 + d1 * d1 + d2 * d2 + d3 * d3);
        float inv = rsqrtf(vs * (1.f / 64.f) + 1e-5f);
        sx[r * 65 + c4 + 0] = d0 * inv * g1[c4 + 0] + b1[c4 + 0];
        sx[r * 65 + c4 + 1] = d1 * inv * g1[c4 + 1] + b1[c4 + 1];
        sx[r * 65 + c4 + 2] = d2 * inv * g1[c4 + 2] + b1[c4 + 2];
        sx[r * 65 + c4 + 3] = d3 * inv * g1[c4 + 3] + b1[c4 + 3];
    }
    __syncthreads();

    int r0 = (tid & 15) * 2;
    int c0 = (tid >> 4) * 6;
    u64 acc2[2][3];
    #pragma unroll
    for (int j = 0; j < 3; j++) {
        u64 bz = *reinterpret_cast<const u64*>(&sb[c0 + 2 * j]);
        acc2[0][j] = bz; acc2[1][j] = bz;
    }
    #pragma unroll 16
    for (int k = 0; k < 64; k++) {
        u64 x20 = f2x_pack(sx[r0 * 65 + k], sx[r0 * 65 + k]);
        u64 x21 = f2x_pack(sx[(r0 + 1) * 65 + k], sx[(r0 + 1) * 65 + k]);
        const float* wr = &sw[k * 192 + c0];
        u64 w0 = *reinterpret_cast<const u64*>(wr);
        u64 w1 = *reinterpret_cast<const u64*>(wr + 2);
        u64 w2 = *reinterpret_cast<const u64*>(wr + 4);
        acc2[0][0] = f2x_fma(x20, w0, acc2[0][0]);
        acc2[0][1] = f2x_fma(x20, w1, acc2[0][1]);
        acc2[0][2] = f2x_fma(x20, w2, acc2[0][2]);
        acc2[1][0] = f2x_fma(x21, w0, acc2[1][0]);
        acc2[1][1] = f2x_fma(x21, w1, acc2[1][1]);
        acc2[1][2] = f2x_fma(x21, w2, acc2[1][2]);
    }
    #pragma unroll
    for (int i = 0; i < 2; i++) {
        u64* outp = reinterpret_cast<u64*>(g_qkv + (size_t)(row0 + r0 + i) * 192 + c0);
        outp[0] = acc2[i][0]; outp[1] = acc2[i][1]; outp[2] = acc2[i][2];
    }
}

__device__ __forceinline__ void knn_body(
    int bidx, const float* __restrict__ coords, const u32* __restrict__ maskw)
{
    float* snx = dyn_smem;
    float* sny = snx + N_;
    float* snz = sny + N_;
    uint2* sbuf = reinterpret_cast<uint2*>(snz + N_);   // [32][64]
    int*   scnt = reinterpret_cast<int*>(sbuf + 32 * 64);

    int b    = bidx >> 7;                // 128 tiles per batch
    int tile = bidx & 127;
    int tid = threadIdx.x;
    const float* cb = coords + (size_t)b * N_ * 3;
    const u32* mb = maskw + (size_t)b * N_;
    for (int i = tid; i < N_; i += 512) {
        float cx = cb[3 * i], cy = cb[3 * i + 1], cz = cb[3 * i + 2];
        if (mb[i] == 0u) cx += 1e5f;     // masked pushed far (d2 ~1e10 >> 768)
        snx[i] = -cx; sny[i] = -cy; snz[i] = -cz;
    }
    __syncthreads();

    int wid = tid >> 5, lane = tid & 31;
    int n0 = tile * 32 + wid * 2;        // queries n0, n0+1

    float q0x = -snx[n0],     q0y = -sny[n0],     q0z = -snz[n0];
    float q1x = -snx[n0 + 1], q1y = -sny[n0 + 1], q1z = -snz[n0 + 1];
    u64 q0x2 = f2x_pack(q0x, q0x), q0y2 = f2x_pack(q0y, q0y), q0z2 = f2x_pack(q0z, q0z);
    u64 q1x2 = f2x_pack(q1x, q1x), q1y2 = f2x_pack(q1y, q1y), q1z2 = f2x_pack(q1z, q1z);

    // pass A: per-lane minima
    float mA0 = 3.4e38f, mA1 = 3.4e38f;
    #pragma unroll 4
    for (int t = 0; t < 64; t++) {
        int j2 = t * 64 + lane * 2;
        u64 nx2 = *reinterpret_cast<const u64*>(snx + j2);
        u64 ny2 = *reinterpret_cast<const u64*>(sny + j2);
        u64 nz2 = *reinterpret_cast<const u64*>(snz + j2);
        {
            u64 dx = f2x_add(q0x2, nx2), dy = f2x_add(q0y2, ny2), dz = f2x_add(q0z2, nz2);
            u64 s2 = f2x_fma(dx, dx, f2x_fma(dy, dy, f2x_mul(dz, dz)));
            float da, db; f2x_unpack(da, db, s2);
            mA0 = fminf(mA0, fminf(da, db));
        }
        {
            u64 dx = f2x_add(q1x2, nx2), dy = f2x_add(q1y2, ny2), dz = f2x_add(q1z2, nz2);
            u64 s2 = f2x_fma(dx, dx, f2x_fma(dy, dy, f2x_mul(dz, dz)));
            float da, db; f2x_unpack(da, db, s2);
            mA1 = fminf(mA1, fminf(da, db));
        }
    }

    // T = 10th smallest of 32 lane minima
    u32 T0, T1;
    {
        u32 cur = __float_as_uint(mA0), mv = 0;
        #pragma unroll
        for (int r = 0; r < KNN_; r++) {
            mv = __reduce_min_sync(0xffffffffu, cur);
            u32 bal = __ballot_sync(0xffffffffu, cur == mv);
            if (lane == __ffs(bal) - 1) cur = 0xffffffffu;
        }
        T0 = mv;
    }
    {
        u32 cur = __float_as_uint(mA1), mv = 0;
        #pragma unroll
        for (int r = 0; r < KNN_; r++) {
            mv = __reduce_min_sync(0xffffffffu, cur);
            u32 bal = __ballot_sync(0xffffffffu, cur == mv);
            if (lane == __ffs(bal) - 1) cur = 0xffffffffu;
        }
        T1 = mv;
    }

    int slot0 = wid * 2, slot1 = wid * 2 + 1;
    if (lane < 2) scnt[wid * 2 + lane] = 0;
    __syncwarp();

    // pass B: push candidates with d2 <= T
    #pragma unroll 2
    for (int t = 0; t < 64; t++) {
        int j2 = t * 64 + lane * 2;
        u64 nx2 = *reinterpret_cast<const u64*>(snx + j2);
        u64 ny2 = *reinterpret_cast<const u64*>(sny + j2);
        u64 nz2 = *reinterpret_cast<const u64*>(snz + j2);
        u64 dx0 = f2x_add(q0x2, nx2), dy0 = f2x_add(q0y2, ny2), dz0 = f2x_add(q0z2, nz2);
        u64 s20 = f2x_fma(dx0, dx0, f2x_fma(dy0, dy0, f2x_mul(dz0, dz0)));
        u64 dx1 = f2x_add(q1x2, nx2), dy1 = f2x_add(q1y2, ny2), dz1 = f2x_add(q1z2, nz2);
        u64 s21 = f2x_fma(dx1, dx1, f2x_fma(dy1, dy1, f2x_mul(dz1, dz1)));
        float a0, b0, a1, b1;
        f2x_unpack(a0, b0, s20);
        f2x_unpack(a1, b1, s21);
        u32 ba0 = __float_as_uint(a0), bb0 = __float_as_uint(b0);
        u32 ba1 = __float_as_uint(a1), bb1 = __float_as_uint(b1);
        bool h00 = ba0 <= T0, h01 = bb0 <= T0;
        bool h10 = ba1 <= T1, h11 = bb1 <= T1;
        if (__any_sync(0xffffffffu, h00 | h01 | h10 | h11)) {
            if (h00) { int p = atomicAdd(&scnt[slot0], 1); if (p < 64) sbuf[slot0 * 64 + p] = make_uint2(ba0, (u32)j2); }
            if (h01) { int p = atomicAdd(&scnt[slot0], 1); if (p < 64) sbuf[slot0 * 64 + p] = make_uint2(bb0, (u32)(j2 + 1)); }
            if (h10) { int p = atomicAdd(&scnt[slot1], 1); if (p < 64) sbuf[slot1 * 64 + p] = make_uint2(ba1, (u32)j2); }
            if (h11) { int p = atomicAdd(&scnt[slot1], 1); if (p < 64) sbuf[slot1 * 64 + p] = make_uint2(bb1, (u32)(j2 + 1)); }
        }
    }
    __syncwarp();

    // exact top-10 per query (stable by (d2, idx))
    #pragma unroll
    for (int q = 0; q < 2; q++) {
        int slot = wid * 2 + q;
        int c = scnt[slot]; if (c > 64) c = 64;
        uint2 e0 = (lane      < c) ? sbuf[slot * 64 + lane]      : make_uint2(0xffffffffu, 0xffffffffu);
        uint2 e1 = (lane + 32 < c) ? sbuf[slot * 64 + lane + 32] : make_uint2(0xffffffffu, 0xffffffffu);
        int* outp = g_nbr + ((size_t)b * N_ + n0 + q) * KNN_;
        #pragma unroll
        for (int r = 0; r < KNN_; r++) {
            u32 mv = __reduce_min_sync(0xffffffffu, e0.x < e1.x ? e0.x : e1.x);
            u32 ci = 0xffffffffu;
            if (e0.x == mv) ci = e0.y;
            if (e1.x == mv && e1.y < ci) ci = e1.y;
            u32 mi = __reduce_min_sync(0xffffffffu, ci);
            if (lane == 0) outp[r] = (int)mi;
            if (e0.x == mv && e0.y == mi) e0.x = 0xffffffffu;
            else if (e1.x == mv && e1.y == mi) e1.x = 0xffffffffu;
        }
    }
}

__global__ __launch_bounds__(512, 2)
void k_front(const float* __restrict__ x,
             const float* __restrict__ g1, const float* __restrict__ b1,
             const float* __restrict__ wqkv, const float* __restrict__ bqkv,
             const float* __restrict__ coords, const u32* __restrict__ maskw)
{
    if (blockIdx.x < 512) qkv_body(blockIdx.x, x, g1, b1, wqkv, bqkv);
    else                  knn_body(blockIdx.x - 512, coords, maskw);
}

// ============ Kernel B: attention + proj + mask + residual ================
// block = 256 threads = 16 half-warp units = 4 rows x 4 heads. Attention o
// kept in smem; 64x64 proj applied in-block (f32x2 over k-pairs, w_proj^T
// staged in smem), then mask+residual -> g_x1.
__global__ __launch_bounds__(256)
void k_attnproj(const float* __restrict__ x, const u32* __restrict__ maskw,
                const float* __restrict__ wp, const float* __restrict__ bp)
{
    __shared__ float swt[64 * 66];   // wproj^T : swt[c*66 + k]
    __shared__ float so_[4 * 68];    // o rows (4 x 64, stride 68)

    int tid = threadIdx.x;
    // stage wproj transposed (global [k][c] -> smem [c][k])
    #pragma unroll
    for (int i = tid; i < 4096; i += 256) {
        int k = i >> 6, c = i & 63;
        swt[c * 66 + k] = wp[i];
    }

    int wid = tid >> 5, lane = tid & 31;
    int sub = lane >> 4, sl = lane & 15;
    int p = wid * 2 + sub;            // 0..15
    int rl = p >> 2;                  // local row 0..3
    int h  = p & 3;
    int grow = blockIdx.x * 4 + rl;   // global row
    int b = grow >> 12;
    size_t row = (size_t)grow;

    // ---- scores over 10 neighbors (lanes sl < 10 of each half)
    int nbrj = 0;
    float s = 0.f;
    u64 key = 0;
    if (sl < KNN_) {
        nbrj = g_nbr[row * KNN_ + sl];
        const float4* kr = reinterpret_cast<const float4*>(
            g_qkv + ((size_t)b * N_ + nbrj) * 192 + 64 + h * 16);
        const float4* qr = reinterpret_cast<const float4*>(g_qkv + row * 192 + h * 16);
        float4 k0 = kr[0], k1 = kr[1], k2 = kr[2], k3 = kr[3];
        float4 q0 = qr[0], q1 = qr[1], q2 = qr[2], q3 = qr[3];
        float acc = q0.x * k0.x;
        acc = fmaf(q0.y, k0.y, acc); acc = fmaf(q0.z, k0.z, acc); acc = fmaf(q0.w, k0.w, acc);
        acc = fmaf(q1.x, k1.x, acc); acc = fmaf(q1.y, k1.y, acc); acc = fmaf(q1.z, k1.z, acc); acc = fmaf(q1.w, k1.w, acc);
        acc = fmaf(q2.x, k2.x, acc); acc = fmaf(q2.y, k2.y, acc); acc = fmaf(q2.z, k2.z, acc); acc = fmaf(q2.w, k2.w, acc);
        acc = fmaf(q3.x, k3.x, acc); acc = fmaf(q3.y, k3.y, acc); acc = fmaf(q3.z, k3.z, acc); acc = fmaf(q3.w, k3.w, acc);
        s = acc * 0.25f;                 // 1/sqrt(16)
        if (maskw[(size_t)b * N_ + nbrj] == 0u) s -= 1e9f;
        u32 bits = __float_as_uint(s);
        u32 ub = (s >= 0.f) ? (bits | 0x80000000u) : ~bits;   // order-preserving, >0
        key = ((u64)ub << 6) | (u64)(63 - sl);
    }

    // ---- stable top-4 within half-warp (max key; tie impossible: sl embedded)
    float wgt[KS_]; int nb[KS_];
    float mx = 0.f;
    #pragma unroll
    for (int r = 0; r < KS_; r++) {
        u64 km = key;
        #pragma unroll
        for (int off = 8; off; off >>= 1) {
            u64 o = __shfl_xor_sync(0xffffffffu, km, off);
            if (o > km) km = o;
        }
        int wsl = 63 - (int)(km & 63);
        int src = sub * 16 + wsl;
        float sv = __shfl_sync(0xffffffffu, s, src);
        nb[r]   = __shfl_sync(0xffffffffu, nbrj, src);
        if (r == 0) mx = sv;
        wgt[r] = __expf(sv - mx);
        if (sl == wsl) key = 0;
    }
    float inv = 1.f / (wgt[0] + wgt[1] + wgt[2] + wgt[3]);

    // ---- V gather (all 16 lanes of each half)
    {
        size_t voff = (size_t)b * N_ * 192 + 128 + h * 16 + sl;
        float o = wgt[0] * g_qkv[voff + (size_t)nb[0] * 192]
                + wgt[1] * g_qkv[voff + (size_t)nb[1] * 192]
                + wgt[2] * g_qkv[voff + (size_t)nb[2] * 192]
                + wgt[3] * g_qkv[voff + (size_t)nb[3] * 192];
        so_[rl * 68 + h * 16 + sl] = o * inv;
    }
    __syncthreads();

    // ---- proj (4 rows x 64 cols), f32x2 over k-pairs
    {
        int r = tid >> 6;            // 0..3
        int c = tid & 63;
        u64 acc2 = 0;
        #pragma unroll 8
        for (int kp = 0; kp < 32; kp++) {
            u64 o2 = *reinterpret_cast<const u64*>(&so_[r * 68 + 2 * kp]);
            u64 w2 = *reinterpret_cast<const u64*>(&swt[c * 66 + 2 * kp]);
            acc2 = f2x_fma(o2, w2, acc2);
        }
        float lo, hi; f2x_unpack(lo, hi, acc2);
        float acc = lo + hi + bp[c];
        int gr = blockIdx.x * 4 + r;
        float m = (maskw[gr] != 0u) ? 0.5f : 0.f;
        g_x1[(size_t)gr * 64 + c] = m * acc + x[(size_t)gr * 64 + c];
    }
}

// ============ Kernel C: LN2 + MLP (persistent, 64-row tiles, f32x2) =======
__device__ __forceinline__ float gelu_fast(float v)
{
    float u = v * v;
    float c = 0.7978845608028654f * v * fmaf(0.044715f, u, 1.f);
    float t;
    asm("tanh.approx.f32 %0, %1;" : "=f"(t) : "f"(c));
    return 0.5f * v * (1.f + t);
}

__global__ __launch_bounds__(512, 1)
void k_mlp(const float* __restrict__ g2, const float* __restrict__ b2p,
           const float* __restrict__ w1, const float* __restrict__ bb1,
           const float* __restrict__ w2, const float* __restrict__ bb2,
           float* __restrict__ out)
{
    float* sw1  = dyn_smem;               // [64][256] natural     16384
    float* sw2t = sw1 + 16384;            // [64][258] w2^T        16512
    float* sxn  = sw2t + 16512;           // [64][65]               4160
    float* sh   = sxn + 4160;             // [64][258]             16512
    float* sb1  = sh + 16512;             // 256
    float* sb2  = sb1 + 256;              // 64
    int tid = threadIdx.x;
    for (int i = tid; i < 4096; i += 512)
        reinterpret_cast<float4*>(sw1)[i] = reinterpret_cast<const float4*>(w1)[i];
    for (int i = tid; i < 16384; i += 512) {   // transpose w2 [256][64] -> [c][k]
        int k = i >> 6, c = i & 63;
        sw2t[c * 258 + k] = w2[i];
    }
    if (tid < 256) sb1[tid] = bb1[tid];
    if (tid < 64)  sb2[tid] = bb2[tid];
    __syncthreads();

    int wid = tid >> 5, lane = tid & 31;

    for (int tile = blockIdx.x; tile < ROWS_ / 64; tile += 148) {
        int row0 = tile * 64;
        // ---- LN2: half-warp per row, 2 passes for 64 rows
        #pragma unroll
        for (int half = 0; half < 2; half++) {
            int r  = half * 32 + 2 * wid + (lane >> 4);
            int c4 = (lane & 15) * 4;
            const float4 xv = *reinterpret_cast<const float4*>(g_x1 + (size_t)(row0 + r) * 64 + c4);
            float s = hsum16(xv.x + xv.y + xv.z + xv.w);
            float mean = s * (1.f / 64.f);
            float d0 = xv.x - mean, d1 = xv.y - mean, d2 = xv.z - mean, d3 = xv.w - mean;
            float vs = hsum16(d0 * d0 + d1 * d1 + d2 * d2 + d3 * d3);
            float iv = rsqrtf(vs * (1.f / 64.f) + 1e-5f);
            sxn[r * 65 + c4 + 0] = d0 * iv * g2[c4 + 0] + b2p[c4 + 0];
            sxn[r * 65 + c4 + 1] = d1 * iv * g2[c4 + 1] + b2p[c4 + 1];
            sxn[r * 65 + c4 + 2] = d2 * iv * g2[c4 + 2] + b2p[c4 + 2];
            sxn[r * 65 + c4 + 3] = d3 * iv * g2[c4 + 3] + b2p[c4 + 3];
        }
        __syncthreads();

        // ---- gemm1: 64x256, thread = 4 rows x 8 cols (c-packed f32x2)
        {
            int r0 = (tid & 15) * 4;
            int c0 = (tid >> 4) * 8;
            u64 acc2[4][4];
            #pragma unroll
            for (int j = 0; j < 4; j++) {
                u64 bz = *reinterpret_cast<const u64*>(&sb1[c0 + 2 * j]);
                acc2[0][j] = bz; acc2[1][j] = bz; acc2[2][j] = bz; acc2[3][j] = bz;
            }
            #pragma unroll 8
            for (int k = 0; k < 64; k++) {
                u64 xr0 = f2x_pack(sxn[(r0 + 0) * 65 + k], sxn[(r0 + 0) * 65 + k]);
                u64 xr1 = f2x_pack(sxn[(r0 + 1) * 65 + k], sxn[(r0 + 1) * 65 + k]);
                u64 xr2 = f2x_pack(sxn[(r0 + 2) * 65 + k], sxn[(r0 + 2) * 65 + k]);
                u64 xr3 = f2x_pack(sxn[(r0 + 3) * 65 + k], sxn[(r0 + 3) * 65 + k]);
                const float* wr = &sw1[k * 256 + c0];
                u64 w0 = *reinterpret_cast<const u64*>(wr);
                u64 w1v = *reinterpret_cast<const u64*>(wr + 2);
                u64 w2v = *reinterpret_cast<const u64*>(wr + 4);
                u64 w3v = *reinterpret_cast<const u64*>(wr + 6);
                acc2[0][0] = f2x_fma(xr0, w0, acc2[0][0]); acc2[0][1] = f2x_fma(xr0, w1v, acc2[0][1]);
                acc2[0][2] = f2x_fma(xr0, w2v, acc2[0][2]); acc2[0][3] = f2x_fma(xr0, w3v, acc2[0][3]);
                acc2[1][0] = f2x_fma(xr1, w0, acc2[1][0]); acc2[1][1] = f2x_fma(xr1, w1v, acc2[1][1]);
                acc2[1][2] = f2x_fma(xr1, w2v, acc2[1][2]); acc2[1][3] = f2x_fma(xr1, w3v, acc2[1][3]);
                acc2[2][0] = f2x_fma(xr2, w0, acc2[2][0]); acc2[2][1] = f2x_fma(xr2, w1v, acc2[2][1]);
                acc2[2][2] = f2x_fma(xr2, w2v, acc2[2][2]); acc2[2][3] = f2x_fma(xr2, w3v, acc2[2][3]);
                acc2[3][0] = f2x_fma(xr3, w0, acc2[3][0]); acc2[3][1] = f2x_fma(xr3, w1v, acc2[3][1]);
                acc2[3][2] = f2x_fma(xr3, w2v, acc2[3][2]); acc2[3][3] = f2x_fma(xr3, w3v, acc2[3][3]);
            }
            #pragma unroll
            for (int i = 0; i < 4; i++) {
                #pragma unroll
                for (int j = 0; j < 4; j++) {
                    float a, bv; f2x_unpack(a, bv, acc2[i][j]);
                    float* hp = &sh[(r0 + i) * 258 + c0 + 2 * j];
                    hp[0] = gelu_fast(a); hp[1] = gelu_fast(bv);
                }
            }
        }
        __syncthreads();

        // ---- gemm2: 64x64, thread = 2 rows x 4 cols (k-packed f32x2)
        {
            int r0 = (tid & 31) * 2;
            int c0 = (tid >> 5) * 4;
            u64 acc2[2][4];
            #pragma unroll
            for (int i = 0; i < 2; i++)
                #pragma unroll
                for (int j = 0; j < 4; j++) acc2[i][j] = 0;
            #pragma unroll 8
            for (int kp = 0; kp < 128; kp++) {
                u64 h0 = *reinterpret_cast<const u64*>(&sh[(r0 + 0) * 258 + 2 * kp]);
                u64 h1 = *reinterpret_cast<const u64*>(&sh[(r0 + 1) * 258 + 2 * kp]);
                u64 wv0 = *reinterpret_cast<const u64*>(&sw2t[(c0 + 0) * 258 + 2 * kp]);
                u64 wv1 = *reinterpret_cast<const u64*>(&sw2t[(c0 + 1) * 258 + 2 * kp]);
                u64 wv2 = *reinterpret_cast<const u64*>(&sw2t[(c0 + 2) * 258 + 2 * kp]);
                u64 wv3 = *reinterpret_cast<const u64*>(&sw2t[(c0 + 3) * 258 + 2 * kp]);
                acc2[0][0] = f2x_fma(h0, wv0, acc2[0][0]); acc2[0][1] = f2x_fma(h0, wv1, acc2[0][1]);
                acc2[0][2] = f2x_fma(h0, wv2, acc2[0][2]); acc2[0][3] = f2x_fma(h0, wv3, acc2[0][3]);
                acc2[1][0] = f2x_fma(h1, wv0, acc2[1][0]); acc2[1][1] = f2x_fma(h1, wv1, acc2[1][1]);
                acc2[1][2] = f2x_fma(h1, wv2, acc2[1][2]); acc2[1][3] = f2x_fma(h1, wv3, acc2[1][3]);
            }
            #pragma unroll
            for (int i = 0; i < 2; i++) {
                size_t gbase = (size_t)(row0 + r0 + i) * 64 + c0;
                float4 xv = *reinterpret_cast<const float4*>(g_x1 + gbase);
                float4 rr;
                float lo, hi;
                f2x_unpack(lo, hi, acc2[i][0]); rr.x = 0.5f * (lo + hi + sb2[c0 + 0]) + xv.x;
                f2x_unpack(lo, hi, acc2[i][1]); rr.y = 0.5f * (lo + hi + sb2[c0 + 1]) + xv.y;
                f2x_unpack(lo, hi, acc2[i][2]); rr.z = 0.5f * (lo + hi + sb2[c0 + 2]) + xv.z;
                f2x_unpack(lo, hi, acc2[i][3]); rr.w = 0.5f * (lo + hi + sb2[c0 + 3]) + xv.w;
                *reinterpret_cast<float4*>(out + gbase) = rr;
            }
        }
        __syncthreads();
    }
}

// ============================== launcher ==================================
extern "C" void kernel_launch(void* const* d_in, const int* in_sizes, int n_in,
                              void* d_out, int out_size)
{
    const float* x      = (const float*)d_in[0];
    const float* coords = (const float*)d_in[1];
    const u32*   maskw  = (const u32*)d_in[2];
    const float* ln1g = (const float*)d_in[3];
    const float* ln1b = (const float*)d_in[4];
    const float* ln2g = (const float*)d_in[5];
    const float* ln2b = (const float*)d_in[6];
    const float* wqkv = (const float*)d_in[7];
    const float* bqkv = (const float*)d_in[8];
    const float* wproj = (const float*)d_in[9];
    const float* bproj = (const float*)d_in[10];
    const float* w1 = (const float*)d_in[11];
    const float* b1 = (const float*)d_in[12];
    const float* w2 = (const float*)d_in[13];
    const float* b2 = (const float*)d_in[14];
    float* out = (float*)d_out;

    static bool attr_done = false;
    if (!attr_done) {
        cudaFuncSetAttribute(k_front, cudaFuncAttributeMaxDynamicSharedMemorySize, 66 * 1024);
        cudaFuncSetAttribute(k_mlp,   cudaFuncAttributeMaxDynamicSharedMemorySize, 216 * 1024);
        attr_done = true;
    }

    size_t smem_front = 66 * 1024;   // max(qkv 58.2KB, knn 65.7KB)
    k_front<<<1024, 512, smem_front>>>(x, ln1g, ln1b, wqkv, bqkv, coords, maskw);

    k_attnproj<<<ROWS_ / 4, 256>>>(x, maskw, wproj, bproj);

    size_t smem_mlp = (16384 + 16512 + 4160 + 16512 + 256 + 64) * sizeof(float);
    k_mlp<<<148, 512, smem_mlp>>>(ln2g, ln2b, w1, b1, w2, b2, out);
}